// round 2
// baseline (speedup 1.0000x reference)
#include <cuda_runtime.h>
#include <math.h>
#include <stdint.h>

#define N_PIX   (512 * 512)
#define BM      16
#define NTHR    256
#define SH_STRIDE 520   // padded row stride (floats) for h1/h2 tiles

// ---------------------------------------------------------------------------
// Accurate sin/cos independent of -use_fast_math: Cody-Waite reduction in
// double (k up to ~65536, reduction error ~1e-12), Cephes fp32 polynomials.
// cos(x) = sin(x + pi/2) -> quadrant shift.
// ---------------------------------------------------------------------------
__device__ __forceinline__ float trig_eval(float x, int cos_flag) {
    double d  = (double)x * 0.63661977236758134308;     // x * 2/pi
    int    ki = __double2int_rn(d);
    float  rf = (float)((double)x - (double)ki * 1.57079632679489661923);
    int    q  = (ki + cos_flag) & 3;
    float  z  = rf * rf;
    // sin poly on [-pi/4, pi/4]
    float s = ((-1.9515295891e-4f * z + 8.3321608736e-3f) * z - 1.6666654611e-1f)
                  * z * rf + rf;
    // cos poly on [-pi/4, pi/4]
    float c = ((2.443315711809948e-5f * z - 1.388731625493765e-3f) * z
                  + 4.166664568298827e-2f) * z * z - 0.5f * z + 1.0f;
    float res = (q & 1) ? c : s;
    return (q & 2) ? -res : res;
}

__device__ float g_b1eff[512];

// ---------------------------------------------------------------------------
// Kernel A: time branch. 1 block, 256 threads.
// phi_t = W2p^T relu(W1p^T posenc_t(idx/300) + b1p) + b2p
// g_b1eff[j] = b1f[j] + sum_k phi_t[k] * W1f[(40+k)*512 + j]
// ---------------------------------------------------------------------------
__global__ void nivr_setup_kernel(const float* __restrict__ W1p,
                                  const float* __restrict__ b1p,
                                  const float* __restrict__ W2p,
                                  const float* __restrict__ b2p,
                                  const float* __restrict__ W1f,
                                  const float* __restrict__ b1f,
                                  const int*   __restrict__ idx_p) {
    __shared__ float sr[32];
    __shared__ float sh[256];
    __shared__ float sphi[128];
    const int tid = threadIdx.x;

    float t = (float)(*idx_p) / 300.0f;
    if (tid < 32) {
        int   l   = tid & 15;
        // (t * 2^l) exact scaling, then * pi_f: one rounding (matches ref order)
        float ang = (t * (float)(1 << l)) * 3.14159265358979323846f;
        sr[tid] = trig_eval(ang, tid >= 16);
    }
    __syncthreads();

    {   // h = relu(r @ W1p + b1p), W1p [32, 256]
        float acc = b1p[tid];
        #pragma unroll
        for (int k = 0; k < 32; k++)
            acc = fmaf(sr[k], W1p[k * 256 + tid], acc);
        sh[tid] = fmaxf(acc, 0.0f);
    }
    __syncthreads();

    if (tid < 128) {   // phi = h @ W2p + b2p, W2p [256, 128]
        float acc = b2p[tid];
        #pragma unroll 4
        for (int k = 0; k < 256; k++)
            acc = fmaf(sh[k], W2p[k * 128 + tid], acc);
        sphi[tid] = acc;
    }
    __syncthreads();

    for (int j = tid; j < 512; j += NTHR) {   // fold phi into layer-1 bias
        float acc = b1f[j];
        #pragma unroll 4
        for (int k = 0; k < 128; k++)
            acc = fmaf(sphi[k], W1f[(40 + k) * 512 + j], acc);
        g_b1eff[j] = acc;
    }
}

// ---------------------------------------------------------------------------
// Kernel B: main MLP over pixels. BM=16 pixels per block, 256 threads.
// Each thread owns output columns (2*tid, 2*tid+1) for all 16 pixels.
// ---------------------------------------------------------------------------
__global__ __launch_bounds__(NTHR, 2)
void nivr_main_kernel(const float* __restrict__ coords,
                      const float* __restrict__ W1f,
                      const float* __restrict__ W2f,
                      const float* __restrict__ b2f,
                      const float* __restrict__ W3f,
                      const float* __restrict__ b3f,
                      float* __restrict__ out) {
    extern __shared__ float smem[];
    float* sC  = smem;                      // [BM * 40]
    float* sH1 = sC  + BM * 40;             // [BM * SH_STRIDE]
    float* sH2 = sH1 + BM * SH_STRIDE;      // [BM * SH_STRIDE]
    float* sW3 = sH2 + BM * SH_STRIDE;      // [512 * 3]
    float* sB1 = sW3 + 512 * 3;             // [512]

    const int tid  = threadIdx.x;
    const int base = blockIdx.x * BM;
    const int j0   = tid * 2;

    for (int i = tid; i < 512 * 3; i += NTHR) sW3[i] = W3f[i];
    for (int i = tid; i < 512; i += NTHR)     sB1[i] = g_b1eff[i];

    // posenc: sC[p][f], f = [sin_x(10), cos_x(10), sin_y(10), cos_y(10)]
    for (int v = tid; v < BM * 40; v += NTHR) {
        int   p     = v / 40;
        int   f     = v % 40;
        int   fl    = f % 20;
        float coord = coords[(base + p) * 2 + (f >= 20)];
        // ((c/512) * 2^l) exact, * pi_f one rounding -> matches reference
        float ang = ((coord * (1.0f / 512.0f)) * (float)(1 << (fl % 10)))
                        * 3.14159265358979323846f;
        sC[p * 40 + f] = trig_eval(ang, fl >= 10);
    }
    __syncthreads();

    // ---- layer 1: h1 = relu(c @ W1f[:40,:] + b1eff) --------------------
    {
        float2 acc[BM];
        float2 binit = make_float2(sB1[j0], sB1[j0 + 1]);
        #pragma unroll
        for (int p = 0; p < BM; p++) acc[p] = binit;

        #pragma unroll 4
        for (int k = 0; k < 40; k++) {
            float2 w = *(const float2*)&W1f[k * 512 + j0];
            #pragma unroll
            for (int p = 0; p < BM; p++) {
                float cv = sC[p * 40 + k];
                acc[p].x = fmaf(cv, w.x, acc[p].x);
                acc[p].y = fmaf(cv, w.y, acc[p].y);
            }
        }
        #pragma unroll
        for (int p = 0; p < BM; p++) {
            float2 r = make_float2(fmaxf(acc[p].x, 0.0f), fmaxf(acc[p].y, 0.0f));
            *(float2*)&sH1[p * SH_STRIDE + j0] = r;
        }
    }
    __syncthreads();

    // ---- layer 2: h2 = relu(h1 @ W2f + b2f) ----------------------------
    {
        float2 acc[BM];
        float2 binit = *(const float2*)&b2f[j0];
        #pragma unroll
        for (int p = 0; p < BM; p++) acc[p] = binit;

        #pragma unroll 2
        for (int kk = 0; kk < 512; kk += 4) {
            const float* wb = &W2f[kk * 512 + j0];
            float2 w0 = *(const float2*)(wb);
            float2 w1 = *(const float2*)(wb + 512);
            float2 w2 = *(const float2*)(wb + 1024);
            float2 w3 = *(const float2*)(wb + 1536);
            #pragma unroll
            for (int p = 0; p < BM; p++) {
                float4 h = *(const float4*)&sH1[p * SH_STRIDE + kk];
                acc[p].x = fmaf(h.x, w0.x, acc[p].x);
                acc[p].y = fmaf(h.x, w0.y, acc[p].y);
                acc[p].x = fmaf(h.y, w1.x, acc[p].x);
                acc[p].y = fmaf(h.y, w1.y, acc[p].y);
                acc[p].x = fmaf(h.z, w2.x, acc[p].x);
                acc[p].y = fmaf(h.z, w2.y, acc[p].y);
                acc[p].x = fmaf(h.w, w3.x, acc[p].x);
                acc[p].y = fmaf(h.w, w3.y, acc[p].y);
            }
        }
        #pragma unroll
        for (int p = 0; p < BM; p++) {
            float2 r = make_float2(fmaxf(acc[p].x, 0.0f), fmaxf(acc[p].y, 0.0f));
            *(float2*)&sH2[p * SH_STRIDE + j0] = r;
        }
    }
    __syncthreads();

    // ---- layer 3: rgb = h2 @ W3f + b3f ---------------------------------
    // 48 outputs, 4-way split-k: 192 threads (warps 0..5 fully active).
    if (tid < 192) {
        int g    = tid >> 2;        // 0..47  -> (pixel, channel)
        int part = tid & 3;         // k-range quarter
        int p    = g / 3;
        int ch   = g % 3;
        float acc = 0.0f;
        int k0 = part * 128;
        #pragma unroll 4
        for (int k = k0; k < k0 + 128; k++)
            acc = fmaf(sH2[p * SH_STRIDE + k], sW3[k * 3 + ch], acc);
        acc += __shfl_xor_sync(0xffffffffu, acc, 1);
        acc += __shfl_xor_sync(0xffffffffu, acc, 2);
        if (part == 0)
            out[ch * N_PIX + base + p] = acc + b3f[ch];
    }
}

// ---------------------------------------------------------------------------
extern "C" void kernel_launch(void* const* d_in, const int* in_sizes, int n_in,
                              void* d_out, int out_size) {
    const float* coords = (const float*)d_in[0];
    const float* W1p    = (const float*)d_in[1];
    const float* b1p    = (const float*)d_in[2];
    const float* W2p    = (const float*)d_in[3];
    const float* b2p    = (const float*)d_in[4];
    const float* W1f    = (const float*)d_in[5];
    const float* b1f    = (const float*)d_in[6];
    const float* W2f    = (const float*)d_in[7];
    const float* b2f    = (const float*)d_in[8];
    const float* W3f    = (const float*)d_in[9];
    const float* b3f    = (const float*)d_in[10];
    const int*   idx    = (const int*)d_in[11];
    float*       out    = (float*)d_out;

    const int smem_bytes =
        (BM * 40 + 2 * BM * SH_STRIDE + 512 * 3 + 512) * (int)sizeof(float);

    // > 48KB dynamic smem requires opt-in (host-side attr, not captured; idempotent)
    cudaFuncSetAttribute(nivr_main_kernel,
                         cudaFuncAttributeMaxDynamicSharedMemorySize, smem_bytes);

    nivr_setup_kernel<<<1, NTHR>>>(W1p, b1p, W2p, b2p, W1f, b1f, idx);
    nivr_main_kernel<<<N_PIX / BM, NTHR, smem_bytes>>>(coords, W1f, W2f, b2f,
                                                       W3f, b3f, out);
}

// round 3
// speedup vs baseline: 1.0018x; 1.0018x over previous
#include <cuda_runtime.h>
#include <math.h>
#include <stdint.h>

#define N_PIX   (512 * 512)
#define BM      16
#define NTHR    256
#define SH_STRIDE 520   // padded row stride (floats) for h1/h2 tiles

// ---------------------------------------------------------------------------
// Accurate sin/cos independent of -use_fast_math: Cody-Waite reduction in
// double (k up to ~65536, reduction error ~1e-12), Cephes fp32 polynomials.
// cos(x) = sin(x + pi/2) -> quadrant shift.
// ---------------------------------------------------------------------------
__device__ __forceinline__ float trig_eval(float x, int cos_flag) {
    double d  = (double)x * 0.63661977236758134308;     // x * 2/pi
    int    ki = __double2int_rn(d);
    float  rf = (float)((double)x - (double)ki * 1.57079632679489661923);
    int    q  = (ki + cos_flag) & 3;
    float  z  = rf * rf;
    // sin poly on [-pi/4, pi/4]
    float s = ((-1.9515295891e-4f * z + 8.3321608736e-3f) * z - 1.6666654611e-1f)
                  * z * rf + rf;
    // cos poly on [-pi/4, pi/4]
    float c = ((2.443315711809948e-5f * z - 1.388731625493765e-3f) * z
                  + 4.166664568298827e-2f) * z * z - 0.5f * z + 1.0f;
    float res = (q & 1) ? c : s;
    return (q & 2) ? -res : res;
}

__device__ float g_b1eff[512];

// ---------------------------------------------------------------------------
// Kernel A: time branch. 1 block, 256 threads.
// phi_t = W2p^T relu(W1p^T posenc_t(idx/300) + b1p) + b2p
// g_b1eff[j] = b1f[j] + sum_k phi_t[k] * W1f[(40+k)*512 + j]
// ---------------------------------------------------------------------------
__global__ void nivr_setup_kernel(const float* __restrict__ W1p,
                                  const float* __restrict__ b1p,
                                  const float* __restrict__ W2p,
                                  const float* __restrict__ b2p,
                                  const float* __restrict__ W1f,
                                  const float* __restrict__ b1f,
                                  const int*   __restrict__ idx_p) {
    __shared__ float sr[32];
    __shared__ float sh[256];
    __shared__ float sphi[128];
    const int tid = threadIdx.x;

    float t = (float)(*idx_p) / 300.0f;
    if (tid < 32) {
        int   l   = tid & 15;
        // (t * 2^l) exact scaling, then * pi_f: one rounding (matches ref order)
        float ang = (t * (float)(1 << l)) * 3.14159265358979323846f;
        sr[tid] = trig_eval(ang, tid >= 16);
    }
    __syncthreads();

    {   // h = relu(r @ W1p + b1p), W1p [32, 256]
        float acc = b1p[tid];
        #pragma unroll
        for (int k = 0; k < 32; k++)
            acc = fmaf(sr[k], W1p[k * 256 + tid], acc);
        sh[tid] = fmaxf(acc, 0.0f);
    }
    __syncthreads();

    if (tid < 128) {   // phi = h @ W2p + b2p, W2p [256, 128]
        float acc = b2p[tid];
        #pragma unroll 4
        for (int k = 0; k < 256; k++)
            acc = fmaf(sh[k], W2p[k * 128 + tid], acc);
        sphi[tid] = acc;
    }
    __syncthreads();

    for (int j = tid; j < 512; j += NTHR) {   // fold phi into layer-1 bias
        float acc = b1f[j];
        #pragma unroll 4
        for (int k = 0; k < 128; k++)
            acc = fmaf(sphi[k], W1f[(40 + k) * 512 + j], acc);
        g_b1eff[j] = acc;
    }
}

// ---------------------------------------------------------------------------
// Kernel B: main MLP over pixels. BM=16 pixels per block, 256 threads.
// Each thread owns output columns (2*tid, 2*tid+1) for all 16 pixels.
// ---------------------------------------------------------------------------
__global__ __launch_bounds__(NTHR, 2)
void nivr_main_kernel(const float* __restrict__ coords,
                      const float* __restrict__ W1f,
                      const float* __restrict__ W2f,
                      const float* __restrict__ b2f,
                      const float* __restrict__ W3f,
                      const float* __restrict__ b3f,
                      float* __restrict__ out) {
    extern __shared__ float smem[];
    float* sC  = smem;                      // [BM * 40]
    float* sH1 = sC  + BM * 40;             // [BM * SH_STRIDE]
    float* sH2 = sH1 + BM * SH_STRIDE;      // [BM * SH_STRIDE]
    float* sW3 = sH2 + BM * SH_STRIDE;      // [512 * 3]
    float* sB1 = sW3 + 512 * 3;             // [512]

    const int tid  = threadIdx.x;
    const int base = blockIdx.x * BM;
    const int j0   = tid * 2;

    for (int i = tid; i < 512 * 3; i += NTHR) sW3[i] = W3f[i];
    for (int i = tid; i < 512; i += NTHR)     sB1[i] = g_b1eff[i];

    // posenc: sC[p][f], f = [sin_x(10), cos_x(10), sin_y(10), cos_y(10)]
    for (int v = tid; v < BM * 40; v += NTHR) {
        int   p     = v / 40;
        int   f     = v % 40;
        int   fl    = f % 20;
        float coord = coords[(base + p) * 2 + (f >= 20)];
        // ((c/512) * 2^l) exact, * pi_f one rounding -> matches reference
        float ang = ((coord * (1.0f / 512.0f)) * (float)(1 << (fl % 10)))
                        * 3.14159265358979323846f;
        sC[p * 40 + f] = trig_eval(ang, fl >= 10);
    }
    __syncthreads();

    // ---- layer 1: h1 = relu(c @ W1f[:40,:] + b1eff) --------------------
    {
        float2 acc[BM];
        float2 binit = make_float2(sB1[j0], sB1[j0 + 1]);
        #pragma unroll
        for (int p = 0; p < BM; p++) acc[p] = binit;

        #pragma unroll 4
        for (int k = 0; k < 40; k++) {
            float2 w = *(const float2*)&W1f[k * 512 + j0];
            #pragma unroll
            for (int p = 0; p < BM; p++) {
                float cv = sC[p * 40 + k];
                acc[p].x = fmaf(cv, w.x, acc[p].x);
                acc[p].y = fmaf(cv, w.y, acc[p].y);
            }
        }
        #pragma unroll
        for (int p = 0; p < BM; p++) {
            float2 r = make_float2(fmaxf(acc[p].x, 0.0f), fmaxf(acc[p].y, 0.0f));
            *(float2*)&sH1[p * SH_STRIDE + j0] = r;
        }
    }
    __syncthreads();

    // ---- layer 2: h2 = relu(h1 @ W2f + b2f) ----------------------------
    {
        float2 acc[BM];
        float2 binit = *(const float2*)&b2f[j0];
        #pragma unroll
        for (int p = 0; p < BM; p++) acc[p] = binit;

        #pragma unroll 2
        for (int kk = 0; kk < 512; kk += 4) {
            const float* wb = &W2f[kk * 512 + j0];
            float2 w0 = *(const float2*)(wb);
            float2 w1 = *(const float2*)(wb + 512);
            float2 w2 = *(const float2*)(wb + 1024);
            float2 w3 = *(const float2*)(wb + 1536);
            #pragma unroll
            for (int p = 0; p < BM; p++) {
                float4 h = *(const float4*)&sH1[p * SH_STRIDE + kk];
                acc[p].x = fmaf(h.x, w0.x, acc[p].x);
                acc[p].y = fmaf(h.x, w0.y, acc[p].y);
                acc[p].x = fmaf(h.y, w1.x, acc[p].x);
                acc[p].y = fmaf(h.y, w1.y, acc[p].y);
                acc[p].x = fmaf(h.z, w2.x, acc[p].x);
                acc[p].y = fmaf(h.z, w2.y, acc[p].y);
                acc[p].x = fmaf(h.w, w3.x, acc[p].x);
                acc[p].y = fmaf(h.w, w3.y, acc[p].y);
            }
        }
        #pragma unroll
        for (int p = 0; p < BM; p++) {
            float2 r = make_float2(fmaxf(acc[p].x, 0.0f), fmaxf(acc[p].y, 0.0f));
            *(float2*)&sH2[p * SH_STRIDE + j0] = r;
        }
    }
    __syncthreads();

    // ---- layer 3: rgb = h2 @ W3f + b3f ---------------------------------
    // 48 outputs, 4-way split-k: 192 threads (warps 0..5 fully active).
    if (tid < 192) {
        int g    = tid >> 2;        // 0..47  -> (pixel, channel)
        int part = tid & 3;         // k-range quarter
        int p    = g / 3;
        int ch   = g % 3;
        float acc = 0.0f;
        int k0 = part * 128;
        #pragma unroll 4
        for (int k = k0; k < k0 + 128; k++)
            acc = fmaf(sH2[p * SH_STRIDE + k], sW3[k * 3 + ch], acc);
        acc += __shfl_xor_sync(0xffffffffu, acc, 1);
        acc += __shfl_xor_sync(0xffffffffu, acc, 2);
        if (part == 0)
            out[ch * N_PIX + base + p] = acc + b3f[ch];
    }
}

// ---------------------------------------------------------------------------
extern "C" void kernel_launch(void* const* d_in, const int* in_sizes, int n_in,
                              void* d_out, int out_size) {
    const float* coords = (const float*)d_in[0];
    const float* W1p    = (const float*)d_in[1];
    const float* b1p    = (const float*)d_in[2];
    const float* W2p    = (const float*)d_in[3];
    const float* b2p    = (const float*)d_in[4];
    const float* W1f    = (const float*)d_in[5];
    const float* b1f    = (const float*)d_in[6];
    const float* W2f    = (const float*)d_in[7];
    const float* b2f    = (const float*)d_in[8];
    const float* W3f    = (const float*)d_in[9];
    const float* b3f    = (const float*)d_in[10];
    const int*   idx    = (const int*)d_in[11];
    float*       out    = (float*)d_out;

    const int smem_bytes =
        (BM * 40 + 2 * BM * SH_STRIDE + 512 * 3 + 512) * (int)sizeof(float);

    // > 48KB dynamic smem requires opt-in (host-side attr, not captured; idempotent)
    cudaFuncSetAttribute(nivr_main_kernel,
                         cudaFuncAttributeMaxDynamicSharedMemorySize, smem_bytes);

    nivr_setup_kernel<<<1, NTHR>>>(W1p, b1p, W2p, b2p, W1f, b1f, idx);
    nivr_main_kernel<<<N_PIX / BM, NTHR, smem_bytes>>>(coords, W1f, W2f, b2f,
                                                       W3f, b3f, out);
}

// round 5
// speedup vs baseline: 2.6131x; 2.6085x over previous
#include <cuda_runtime.h>
#include <math.h>
#include <stdint.h>

#define N_PIX (512 * 512)
#define NTHR  256

// ---------------------------------------------------------------------------
// Device scratch (static: no allocations allowed)
// ---------------------------------------------------------------------------
__device__ float    g_b1eff[512];        // b1f + phi_t @ W1f[40:,:]
__device__ float    g_Ax[512 * 512];     // posenc_x(c) @ W1f[0:20,:] + b1eff
__device__ float    g_Ay[512 * 512];     // posenc_y(c) @ W1f[20:40,:]
__device__ uint32_t g_W2F[512 * 512];    // W2 in mma-fragment-major tf32 layout

__device__ __forceinline__ uint32_t f2tf32(float x) {
    uint32_t u;
    asm("cvt.rna.tf32.f32 %0, %1;" : "=r"(u) : "f"(x));
    return u;
}

// m16n8k8 tf32 mma: D += A @ B  (A row-major frag, B col-major frag)
#define MMA_TF32(d, a, b)                                                      \
    asm volatile("mma.sync.aligned.m16n8k8.row.col.f32.tf32.tf32.f32 "         \
                 "{%0,%1,%2,%3},{%4,%5,%6,%7},{%8,%9},{%0,%1,%2,%3};"          \
                 : "+f"((d)[0]), "+f"((d)[1]), "+f"((d)[2]), "+f"((d)[3])      \
                 : "r"((a).x), "r"((a).y), "r"((a).z), "r"((a).w),             \
                   "r"((b).x), "r"((b).y))

// ---------------------------------------------------------------------------
// Accurate sin/cos (flag-independent): Cody-Waite in double + Cephes fp32
// ---------------------------------------------------------------------------
__device__ __forceinline__ float trig_eval(float x, int cos_flag) {
    double d  = (double)x * 0.63661977236758134308;
    int    ki = __double2int_rn(d);
    float  rf = (float)((double)x - (double)ki * 1.57079632679489661923);
    int    q  = (ki + cos_flag) & 3;
    float  z  = rf * rf;
    float s = ((-1.9515295891e-4f * z + 8.3321608736e-3f) * z - 1.6666654611e-1f)
                  * z * rf + rf;
    float c = ((2.443315711809948e-5f * z - 1.388731625493765e-3f) * z
                  + 4.166664568298827e-2f) * z * z - 0.5f * z + 1.0f;
    float res = (q & 1) ? c : s;
    return (q & 2) ? -res : res;
}

// ---------------------------------------------------------------------------
// Setup 1: time branch -> g_b1eff  (1 block)
// ---------------------------------------------------------------------------
__global__ void nivr_setup_kernel(const float* __restrict__ W1p,
                                  const float* __restrict__ b1p,
                                  const float* __restrict__ W2p,
                                  const float* __restrict__ b2p,
                                  const float* __restrict__ W1f,
                                  const float* __restrict__ b1f,
                                  const int*   __restrict__ idx_p) {
    __shared__ float sr[32];
    __shared__ float sh[256];
    __shared__ float sphi[128];
    const int tid = threadIdx.x;

    float t = (float)(*idx_p) / 300.0f;
    if (tid < 32) {
        int l = tid & 15;
        float ang = (t * (float)(1 << l)) * 3.14159265358979323846f;
        sr[tid] = trig_eval(ang, tid >= 16);
    }
    __syncthreads();
    {
        float acc = b1p[tid];
        #pragma unroll
        for (int k = 0; k < 32; k++)
            acc = fmaf(sr[k], W1p[k * 256 + tid], acc);
        sh[tid] = fmaxf(acc, 0.0f);
    }
    __syncthreads();
    if (tid < 128) {
        float acc = b2p[tid];
        #pragma unroll 4
        for (int k = 0; k < 256; k++)
            acc = fmaf(sh[k], W2p[k * 128 + tid], acc);
        sphi[tid] = acc;
    }
    __syncthreads();
    for (int j = tid; j < 512; j += NTHR) {
        float acc = b1f[j];
        #pragma unroll 4
        for (int k = 0; k < 128; k++)
            acc = fmaf(sphi[k], W1f[(40 + k) * 512 + j], acc);
        g_b1eff[j] = acc;
    }
}

// ---------------------------------------------------------------------------
// Setup 2: posenc@W1 tables (b1eff folded into Ax) + W2 fragment permutation.
// grid = 1536 blocks: [0,1024) tables, [1024,1536) W2F.
//
// W2F layout: for element (n, k) of W2T[n][k] = W2f[k*512+n]:
//   idx = ((k>>3)*64 + (n>>3))*32 + (n&7)*4 + (k&3), reg = (k>>2)&1
//   g_W2F[idx*2 + reg]  -> warp loads uint2 per (k8-group, n8-tile), coalesced.
// ---------------------------------------------------------------------------
__global__ void nivr_tables_kernel(const float* __restrict__ W1f,
                                   const float* __restrict__ W2f) {
    const int b = blockIdx.x, tid = threadIdx.x;
    if (b < 1024) {
        const int axis = b >> 9;
        const int c    = b & 511;
        __shared__ float pe[20];
        if (tid < 20) {
            int l = tid % 10;
            float ang = (((float)c * (1.0f / 512.0f)) * (float)(1 << l))
                            * 3.14159265358979323846f;
            pe[tid] = trig_eval(ang, tid >= 10);
        }
        __syncthreads();
        const float* Wr  = W1f + axis * 20 * 512;
        float*       dst = (axis ? g_Ay : g_Ax) + c * 512;
        for (int j = tid; j < 512; j += NTHR) {
            float acc = axis ? 0.0f : g_b1eff[j];
            #pragma unroll
            for (int f = 0; f < 20; f++)
                acc = fmaf(pe[f], Wr[f * 512 + j], acc);
            dst[j] = acc;
        }
    } else {
        const int n = b - 1024;
        for (int k = tid; k < 512; k += NTHR) {
            int idx = ((k >> 3) * 64 + (n >> 3)) * 32 + (n & 7) * 4 + (k & 3);
            int reg = (k >> 2) & 1;
            g_W2F[idx * 2 + reg] = f2tf32(W2f[k * 512 + n]);
        }
    }
}

// ---------------------------------------------------------------------------
// Main: CTA = 64 pixels, 8 warps (2M x 4N), warp tile 32x64, N in 2 halves.
//   h1 = relu(Ax[x] + Ay[y])  (b1eff pre-folded), tf32
//   H2 = relu(h1 @ W2 + b2);  rgb = H2 @ W3 + b3  (fp32 epilogue)
// ---------------------------------------------------------------------------
__global__ __launch_bounds__(NTHR)
void nivr_mma_kernel(const float* __restrict__ coords,
                     const float* __restrict__ b2f,
                     const float* __restrict__ W3f,
                     const float* __restrict__ b3f,
                     float* __restrict__ out) {
    __shared__ uint32_t sA[2048];         // A' fragment-major: [kk4][mt4][lane32][4]
    __shared__ float    sW3[512 * 3];
    __shared__ float    sB2[512];
    __shared__ float    sPart[4][64][3];
    __shared__ int      sX[64], sY[64];

    const int tid   = threadIdx.x;
    const int wid   = tid >> 5;
    const int lane  = tid & 31;
    const int g     = lane >> 2;
    const int tig   = lane & 3;
    const int warpM = wid >> 2;           // 0..1
    const int warpN = wid & 3;            // 0..3
    const int pix0  = blockIdx.x * 64;

    if (tid < 64) {
        sX[tid] = (int)coords[(pix0 + tid) * 2 + 0];
        sY[tid] = (int)coords[(pix0 + tid) * 2 + 1];
    }
    for (int i = tid; i < 1536; i += NTHR) sW3[i] = W3f[i];
    for (int i = tid; i < 512;  i += NTHR) sB2[i] = b2f[i];
    __syncthreads();

    float rp[4][3];                       // rgb partials per (mt, row-half)
    #pragma unroll
    for (int i = 0; i < 4; i++)
        rp[i][0] = rp[i][1] = rp[i][2] = 0.0f;

    // producer-role constants: thread <-> (row r, k-subchunk kk)
    const int pr  = tid & 63;
    const int pkk = tid >> 6;
    const int pmt = pr >> 4, pg = pr & 7, prh = (pr >> 3) & 1;
    const float* axp_base = g_Ax + (size_t)sX[pr] * 512;
    const float* ayp_base = g_Ay + (size_t)sY[pr] * 512;
    const uint32_t pbase  = (uint32_t)(((pkk * 4 + pmt) * 32 + pg * 4) * 4);

    for (int nh = 0; nh < 2; nh++) {
        const int nb8 = nh * 32 + warpN * 8;    // n8-tile base for this warp
        float acc[2][8][4];
        #pragma unroll
        for (int m = 0; m < 2; m++)
            #pragma unroll
            for (int n = 0; n < 8; n++)
                acc[m][n][0] = acc[m][n][1] = acc[m][n][2] = acc[m][n][3] = 0.0f;

        for (int kc = 0; kc < 16; kc++) {
            __syncthreads();                    // A buffer free
            // ---- produce A' chunk (fragment-major, tf32) ------------------
            {
                const int cb = kc * 32 + pkk * 8;
                float4 ax0 = *(const float4*)(axp_base + cb);
                float4 ax1 = *(const float4*)(axp_base + cb + 4);
                float4 ay0 = *(const float4*)(ayp_base + cb);
                float4 ay1 = *(const float4*)(ayp_base + cb + 4);
                float v[8] = { ax0.x + ay0.x, ax0.y + ay0.y,
                               ax0.z + ay0.z, ax0.w + ay0.w,
                               ax1.x + ay1.x, ax1.y + ay1.y,
                               ax1.z + ay1.z, ax1.w + ay1.w };
                #pragma unroll
                for (int t = 0; t < 8; t++) {
                    int reg = ((t >> 2) << 1) | prh;
                    sA[pbase + (t & 3) * 4 + reg] =
                        f2tf32(fmaxf(v[t], 0.0f));
                }
            }
            __syncthreads();                    // A chunk ready
            // ---- consume: 64 MMAs/warp, B frags straight from L2 ----------
            #pragma unroll
            for (int kk = 0; kk < 4; kk++) {
                uint4 afr[2];
                #pragma unroll
                for (int m = 0; m < 2; m++)
                    afr[m] = *(const uint4*)
                        &sA[((kk * 4 + warpM * 2 + m) * 32 + lane) * 4];
                const uint2* bptr = (const uint2*)g_W2F
                                  + ((kc * 4 + kk) * 64 + nb8) * 32 + lane;
                #pragma unroll
                for (int nt = 0; nt < 8; nt++) {
                    uint2 b = bptr[nt * 32];
                    MMA_TF32(acc[0][nt], afr[0], b);
                    MMA_TF32(acc[1][nt], afr[1], b);
                }
            }
        }
        // ---- epilogue for this N-half: relu+bias, fold into rgb partials --
        #pragma unroll
        for (int m = 0; m < 2; m++)
            #pragma unroll
            for (int nt = 0; nt < 8; nt++) {
                int c0 = nh * 256 + warpN * 64 + nt * 8 + tig * 2;
                float h0 = fmaxf(acc[m][nt][0] + sB2[c0],     0.0f);
                float h1 = fmaxf(acc[m][nt][1] + sB2[c0 + 1], 0.0f);
                float h2 = fmaxf(acc[m][nt][2] + sB2[c0],     0.0f);
                float h3 = fmaxf(acc[m][nt][3] + sB2[c0 + 1], 0.0f);
                #pragma unroll
                for (int ch = 0; ch < 3; ch++) {
                    float w0 = sW3[c0 * 3 + ch], w1 = sW3[(c0 + 1) * 3 + ch];
                    rp[m * 2 + 0][ch] = fmaf(h0, w0, fmaf(h1, w1, rp[m * 2 + 0][ch]));
                    rp[m * 2 + 1][ch] = fmaf(h2, w0, fmaf(h3, w1, rp[m * 2 + 1][ch]));
                }
            }
    }

    // ---- reduce over tig within quad, then across N-warps via smem --------
    #pragma unroll
    for (int i = 0; i < 4; i++)
        #pragma unroll
        for (int ch = 0; ch < 3; ch++) {
            rp[i][ch] += __shfl_xor_sync(0xffffffffu, rp[i][ch], 1);
            rp[i][ch] += __shfl_xor_sync(0xffffffffu, rp[i][ch], 2);
        }
    if (tig == 0) {
        #pragma unroll
        for (int m = 0; m < 2; m++)
            #pragma unroll
            for (int rh = 0; rh < 2; rh++) {
                int row = warpM * 32 + m * 16 + rh * 8 + g;
                #pragma unroll
                for (int ch = 0; ch < 3; ch++)
                    sPart[warpN][row][ch] = rp[m * 2 + rh][ch];
            }
    }
    __syncthreads();
    if (tid < 64) {
        #pragma unroll
        for (int ch = 0; ch < 3; ch++) {
            float s = sPart[0][tid][ch] + sPart[1][tid][ch]
                    + sPart[2][tid][ch] + sPart[3][tid][ch] + b3f[ch];
            out[ch * N_PIX + pix0 + tid] = s;
        }
    }
}

// ---------------------------------------------------------------------------
extern "C" void kernel_launch(void* const* d_in, const int* in_sizes, int n_in,
                              void* d_out, int out_size) {
    const float* coords = (const float*)d_in[0];
    const float* W1p    = (const float*)d_in[1];
    const float* b1p    = (const float*)d_in[2];
    const float* W2p    = (const float*)d_in[3];
    const float* b2p    = (const float*)d_in[4];
    const float* W1f    = (const float*)d_in[5];
    const float* b1f    = (const float*)d_in[6];
    const float* W2f    = (const float*)d_in[7];
    const float* b2f    = (const float*)d_in[8];
    const float* W3f    = (const float*)d_in[9];
    const float* b3f    = (const float*)d_in[10];
    const int*   idx    = (const int*)d_in[11];
    float*       out    = (float*)d_out;

    nivr_setup_kernel<<<1, NTHR>>>(W1p, b1p, W2p, b2p, W1f, b1f, idx);
    nivr_tables_kernel<<<1536, NTHR>>>(W1f, W2f);
    nivr_mma_kernel<<<N_PIX / 64, NTHR>>>(coords, b2f, W3f, b3f, out);
}

// round 6
// speedup vs baseline: 5.8721x; 2.2472x over previous
#include <cuda_runtime.h>
#include <cuda_fp16.h>
#include <math.h>
#include <stdint.h>

#define N_PIX (512 * 512)
#define NTHR  256

// ---------------------------------------------------------------------------
// Device scratch (no allocations allowed)
// ---------------------------------------------------------------------------
__device__ float    g_b1eff[512];        // b1f + phi_t @ W1f[40:,:]
__device__ float    g_Ax[512 * 512];     // posenc_x(c) @ W1f[0:20,:]
__device__ float    g_Ay[512 * 512];     // posenc_y(c) @ W1f[20:40,:]
__device__ uint32_t g_W2H[512 * 256];    // W2 fp16, mma-fragment-major

// m16n8k16 fp16 mma, fp32 acc: D += A @ B (A row-major frag, B col-major frag)
#define MMA_F16(d, a, b)                                                       \
    asm volatile("mma.sync.aligned.m16n8k16.row.col.f32.f16.f16.f32 "          \
                 "{%0,%1,%2,%3},{%4,%5,%6,%7},{%8,%9},{%0,%1,%2,%3};"          \
                 : "+f"((d)[0]), "+f"((d)[1]), "+f"((d)[2]), "+f"((d)[3])      \
                 : "r"((a).x), "r"((a).y), "r"((a).z), "r"((a).w),             \
                   "r"((b).x), "r"((b).y))

__device__ __forceinline__ uint32_t h2u(float a, float b) {
    __half2 h = __floats2half2_rn(a, b);
    return *(uint32_t*)&h;
}
__device__ __forceinline__ float relu_f(float x) { return fmaxf(x, 0.0f); }

// ---------------------------------------------------------------------------
// Accurate sin/cos (flag-independent): Cody-Waite in double + Cephes fp32
// ---------------------------------------------------------------------------
__device__ __forceinline__ float trig_eval(float x, int cos_flag) {
    double d  = (double)x * 0.63661977236758134308;
    int    ki = __double2int_rn(d);
    float  rf = (float)((double)x - (double)ki * 1.57079632679489661923);
    int    q  = (ki + cos_flag) & 3;
    float  z  = rf * rf;
    float s = ((-1.9515295891e-4f * z + 8.3321608736e-3f) * z - 1.6666654611e-1f)
                  * z * rf + rf;
    float c = ((2.443315711809948e-5f * z - 1.388731625493765e-3f) * z
                  + 4.166664568298827e-2f) * z * z - 0.5f * z + 1.0f;
    float res = (q & 1) ? c : s;
    return (q & 2) ? -res : res;
}

// ---------------------------------------------------------------------------
// Setup (single launch, 1537 blocks):
//   blocks [0,1024):    Ax / Ay tables (NO b1eff fold)
//   blocks [1024,1536): W2 -> fp16 fragment-major g_W2H
//   block  1536:        time branch -> g_b1eff
//
// W2H packing for element (n, k), value W2f[k*512+n]:
//   k16 = k>>4, n8 = n>>3, lane = (n&7)*4 + ((k&7)>>1), reg = (k>>3)&1,
//   half-position = k&1 (lo = even k).
//   uint32 index = ((k16*64 + n8)*32 + lane)*2 + reg
// ---------------------------------------------------------------------------
__global__ void nivr_prep_kernel(const float* __restrict__ W1p,
                                 const float* __restrict__ b1p,
                                 const float* __restrict__ W2p,
                                 const float* __restrict__ b2p,
                                 const float* __restrict__ W1f,
                                 const float* __restrict__ b1f,
                                 const float* __restrict__ W2f,
                                 const int*   __restrict__ idx_p) {
    const int b = blockIdx.x, tid = threadIdx.x;
    if (b < 1024) {
        const int axis = b >> 9;
        const int c    = b & 511;
        __shared__ float pe[20];
        if (tid < 20) {
            int l = tid % 10;
            float ang = (((float)c * (1.0f / 512.0f)) * (float)(1 << l))
                            * 3.14159265358979323846f;
            pe[tid] = trig_eval(ang, tid >= 10);
        }
        __syncthreads();
        const float* Wr  = W1f + axis * 20 * 512;
        float*       dst = (axis ? g_Ay : g_Ax) + c * 512;
        for (int j = tid; j < 512; j += NTHR) {
            float acc = 0.0f;
            #pragma unroll
            for (int f = 0; f < 20; f++)
                acc = fmaf(pe[f], Wr[f * 512 + j], acc);
            dst[j] = acc;
        }
    } else if (b < 1536) {
        const int n  = b - 1024;
        const int k  = tid * 2;             // even k; pack (k, k+1)
        float lo = W2f[(size_t)k * 512 + n];
        float hi = W2f[(size_t)(k + 1) * 512 + n];
        int k16  = k >> 4;
        int lane = (n & 7) * 4 + ((k & 7) >> 1);
        int reg  = (k >> 3) & 1;
        g_W2H[(((k16 * 64) + (n >> 3)) * 32 + lane) * 2 + reg] = h2u(lo, hi);
    } else {
        __shared__ float sr[32];
        __shared__ float sh[256];
        __shared__ float sphi[128];
        float t = (float)(*idx_p) / 300.0f;
        if (tid < 32) {
            int l = tid & 15;
            float ang = (t * (float)(1 << l)) * 3.14159265358979323846f;
            sr[tid] = trig_eval(ang, tid >= 16);
        }
        __syncthreads();
        {
            float acc = b1p[tid];
            #pragma unroll
            for (int k = 0; k < 32; k++)
                acc = fmaf(sr[k], W1p[k * 256 + tid], acc);
            sh[tid] = fmaxf(acc, 0.0f);
        }
        __syncthreads();
        if (tid < 128) {
            float acc = b2p[tid];
            #pragma unroll 4
            for (int k = 0; k < 256; k++)
                acc = fmaf(sh[k], W2p[k * 128 + tid], acc);
            sphi[tid] = acc;
        }
        __syncthreads();
        for (int j = tid; j < 512; j += NTHR) {
            float acc = b1f[j];
            #pragma unroll 4
            for (int k = 0; k < 128; k++)
                acc = fmaf(sphi[k], W1f[(40 + k) * 512 + j], acc);
            g_b1eff[j] = acc;
        }
    }
}

// ---------------------------------------------------------------------------
// Main: CTA = 64 pixels, 8 warps all along N (warp tile m64 x n64).
//   h1 = relu(Ax[x] + Ay[y] + b1eff), fp16 A chunks in smem (double-buffered)
//   B fp16 fragment-major straight from L2 (each element once per CTA)
//   H2 = relu(h1 @ W2 + b2);  rgb = H2 @ W3 + b3 (fp32 epilogue, folded)
// ---------------------------------------------------------------------------
__global__ __launch_bounds__(NTHR)
void nivr_mma_kernel(const float* __restrict__ coords,
                     const float* __restrict__ b2f,
                     const float* __restrict__ W3f,
                     const float* __restrict__ b3f,
                     float* __restrict__ out) {
    __shared__ uint32_t sA[2][1024];      // [buf][(kt*4+mt)*32+lane] as uint4
    __shared__ float    sB1[512];
    __shared__ float    sB2[512];
    __shared__ float    sW3[512 * 3];
    __shared__ float    sPart[8][64][3];
    __shared__ int      sX[64], sY[64];

    const int tid  = threadIdx.x;
    const int wid  = tid >> 5;            // warpN: 0..7 (cols wid*64..+63)
    const int lane = tid & 31;
    const int g    = lane >> 2;
    const int tg   = lane & 3;
    const int pix0 = blockIdx.x * 64;

    if (tid < 64) {
        sX[tid] = (int)coords[(pix0 + tid) * 2 + 0];
        sY[tid] = (int)coords[(pix0 + tid) * 2 + 1];
    }
    for (int i = tid; i < 512;  i += NTHR) { sB1[i] = g_b1eff[i]; sB2[i] = b2f[i]; }
    for (int i = tid; i < 1536; i += NTHR) sW3[i] = W3f[i];
    __syncthreads();

    // ---- producer role: thread -> (kt, mt, lane') slot ---------------------
    const int pkt  = tid >> 7;            // 0..1 (k16 within 32-chunk)
    const int pmt  = (tid >> 5) & 3;      // m16 tile
    const int pln  = tid & 31;
    const int pg   = pln >> 2, ptg = pln & 3;
    const int p0   = pmt * 16 + pg, p1 = p0 + 8;
    const float* ax0 = g_Ax + (size_t)sX[p0] * 512;
    const float* ay0 = g_Ay + (size_t)sY[p0] * 512;
    const float* ax1 = g_Ax + (size_t)sX[p1] * 512;
    const float* ay1 = g_Ay + (size_t)sY[p1] * 512;
    const int koff = pkt * 16 + ptg * 2;
    const int slot = (pkt * 4 + pmt) * 32 + pln;

    // ---- produce chunk kc = 0 ---------------------------------------------
    {
        const int kb = koff;
        float2 xa = *(const float2*)(ax0 + kb), ya = *(const float2*)(ay0 + kb);
        float2 xb = *(const float2*)(ax0 + kb + 8), yb = *(const float2*)(ay0 + kb + 8);
        float2 xc = *(const float2*)(ax1 + kb), yc = *(const float2*)(ay1 + kb);
        float2 xd = *(const float2*)(ax1 + kb + 8), yd = *(const float2*)(ay1 + kb + 8);
        float2 ba = *(const float2*)(sB1 + kb), bb = *(const float2*)(sB1 + kb + 8);
        uint4 v;
        v.x = h2u(relu_f(xa.x + ya.x + ba.x), relu_f(xa.y + ya.y + ba.y));
        v.y = h2u(relu_f(xc.x + yc.x + ba.x), relu_f(xc.y + yc.y + ba.y));
        v.z = h2u(relu_f(xb.x + yb.x + bb.x), relu_f(xb.y + yb.y + bb.y));
        v.w = h2u(relu_f(xd.x + yd.x + bb.x), relu_f(xd.y + yd.y + bb.y));
        ((uint4*)sA[0])[slot] = v;
    }
    __syncthreads();

    float acc[4][8][4];
    #pragma unroll
    for (int m = 0; m < 4; m++)
        #pragma unroll
        for (int n = 0; n < 8; n++)
            acc[m][n][0] = acc[m][n][1] = acc[m][n][2] = acc[m][n][3] = 0.0f;

    for (int kc = 0; kc < 16; kc++) {
        const int buf = kc & 1;
        // ---- prefetch next A chunk (global loads in flight during MMA) ----
        float2 xa, ya, xb, yb, xc, yc, xd, yd, ba, bb;
        if (kc < 15) {
            const int kb = (kc + 1) * 32 + koff;
            xa = *(const float2*)(ax0 + kb);     ya = *(const float2*)(ay0 + kb);
            xb = *(const float2*)(ax0 + kb + 8); yb = *(const float2*)(ay0 + kb + 8);
            xc = *(const float2*)(ax1 + kb);     yc = *(const float2*)(ay1 + kb);
            xd = *(const float2*)(ax1 + kb + 8); yd = *(const float2*)(ay1 + kb + 8);
            ba = *(const float2*)(sB1 + kb);     bb = *(const float2*)(sB1 + kb + 8);
        }
        // ---- MMA: 2 k16-steps x 8 n-tiles x 4 m-tiles ----------------------
        #pragma unroll
        for (int kt = 0; kt < 2; kt++) {
            uint4 af[4];
            #pragma unroll
            for (int m = 0; m < 4; m++)
                af[m] = ((const uint4*)sA[buf])[(kt * 4 + m) * 32 + lane];
            const uint2* bp = (const uint2*)g_W2H
                            + (((kc * 2 + kt) * 64) + wid * 8) * 32 + lane;
            #pragma unroll
            for (int nt = 0; nt < 8; nt++) {
                uint2 bfr = bp[nt * 32];
                MMA_F16(acc[0][nt], af[0], bfr);
                MMA_F16(acc[1][nt], af[1], bfr);
                MMA_F16(acc[2][nt], af[2], bfr);
                MMA_F16(acc[3][nt], af[3], bfr);
            }
        }
        // ---- store prefetched chunk into the other buffer ------------------
        if (kc < 15) {
            uint4 v;
            v.x = h2u(relu_f(xa.x + ya.x + ba.x), relu_f(xa.y + ya.y + ba.y));
            v.y = h2u(relu_f(xc.x + yc.x + ba.x), relu_f(xc.y + yc.y + ba.y));
            v.z = h2u(relu_f(xb.x + yb.x + bb.x), relu_f(xb.y + yb.y + bb.y));
            v.w = h2u(relu_f(xd.x + yd.x + bb.x), relu_f(xd.y + yd.y + bb.y));
            ((uint4*)sA[buf ^ 1])[slot] = v;
        }
        __syncthreads();
    }

    // ---- epilogue: relu+bias, fold layer-3 into rgb partials ---------------
    float rp[8][3];
    #pragma unroll
    for (int i = 0; i < 8; i++) rp[i][0] = rp[i][1] = rp[i][2] = 0.0f;

    #pragma unroll
    for (int m = 0; m < 4; m++)
        #pragma unroll
        for (int nt = 0; nt < 8; nt++) {
            int c0 = wid * 64 + nt * 8 + tg * 2;
            float h0 = relu_f(acc[m][nt][0] + sB2[c0]);
            float h1 = relu_f(acc[m][nt][1] + sB2[c0 + 1]);
            float h2 = relu_f(acc[m][nt][2] + sB2[c0]);
            float h3 = relu_f(acc[m][nt][3] + sB2[c0 + 1]);
            #pragma unroll
            for (int ch = 0; ch < 3; ch++) {
                float w0 = sW3[c0 * 3 + ch], w1 = sW3[(c0 + 1) * 3 + ch];
                rp[m * 2 + 0][ch] = fmaf(h0, w0, fmaf(h1, w1, rp[m * 2 + 0][ch]));
                rp[m * 2 + 1][ch] = fmaf(h2, w0, fmaf(h3, w1, rp[m * 2 + 1][ch]));
            }
        }

    #pragma unroll
    for (int i = 0; i < 8; i++)
        #pragma unroll
        for (int ch = 0; ch < 3; ch++) {
            rp[i][ch] += __shfl_xor_sync(0xffffffffu, rp[i][ch], 1);
            rp[i][ch] += __shfl_xor_sync(0xffffffffu, rp[i][ch], 2);
        }
    if (tg == 0) {
        #pragma unroll
        for (int m = 0; m < 4; m++)
            #pragma unroll
            for (int rh = 0; rh < 2; rh++) {
                int row = m * 16 + rh * 8 + g;
                #pragma unroll
                for (int ch = 0; ch < 3; ch++)
                    sPart[wid][row][ch] = rp[m * 2 + rh][ch];
            }
    }
    __syncthreads();
    if (tid < 64) {
        #pragma unroll
        for (int ch = 0; ch < 3; ch++) {
            float s = b3f[ch];
            #pragma unroll
            for (int w = 0; w < 8; w++) s += sPart[w][tid][ch];
            out[ch * N_PIX + pix0 + tid] = s;
        }
    }
}

// ---------------------------------------------------------------------------
extern "C" void kernel_launch(void* const* d_in, const int* in_sizes, int n_in,
                              void* d_out, int out_size) {
    const float* coords = (const float*)d_in[0];
    const float* W1p    = (const float*)d_in[1];
    const float* b1p    = (const float*)d_in[2];
    const float* W2p    = (const float*)d_in[3];
    const float* b2p    = (const float*)d_in[4];
    const float* W1f    = (const float*)d_in[5];
    const float* b1f    = (const float*)d_in[6];
    const float* W2f    = (const float*)d_in[7];
    const float* b2f    = (const float*)d_in[8];
    const float* W3f    = (const float*)d_in[9];
    const float* b3f    = (const float*)d_in[10];
    const int*   idx    = (const int*)d_in[11];
    float*       out    = (float*)d_out;

    nivr_prep_kernel<<<1537, NTHR>>>(W1p, b1p, W2p, b2p, W1f, b1f, W2f, idx);
    nivr_mma_kernel<<<N_PIX / 64, NTHR>>>(coords, b2f, W3f, b3f, out);
}

// round 8
// speedup vs baseline: 6.8079x; 1.1594x over previous
#include <cuda_runtime.h>
#include <cuda_fp16.h>
#include <math.h>
#include <stdint.h>

#define N_PIX (512 * 512)
#define NTHR  256

// ---------------------------------------------------------------------------
// Device scratch (no allocations allowed)
// ---------------------------------------------------------------------------
__device__ float    g_b1eff[512];        // b1f + phi_t @ W1f[40:,:]
__device__ float    g_Ax[512 * 512];     // posenc_x(c) @ W1f[0:20,:]
__device__ float    g_Ay[512 * 512];     // posenc_y(c) @ W1f[20:40,:]
__device__ uint32_t g_W2H[512 * 256];    // W2 fp16, uint4-fragment-major

// m16n8k16 fp16 mma, fp32 acc
#define MMA_F16(d, a, b0, b1)                                                  \
    asm volatile("mma.sync.aligned.m16n8k16.row.col.f32.f16.f16.f32 "          \
                 "{%0,%1,%2,%3},{%4,%5,%6,%7},{%8,%9},{%0,%1,%2,%3};"          \
                 : "+f"((d)[0]), "+f"((d)[1]), "+f"((d)[2]), "+f"((d)[3])      \
                 : "r"((a).x), "r"((a).y), "r"((a).z), "r"((a).w),             \
                   "r"(b0), "r"(b1))

__device__ __forceinline__ uint32_t h2u(float a, float b) {
    __half2 h = __floats2half2_rn(a, b);
    return *(uint32_t*)&h;
}
__device__ __forceinline__ float relu_f(float x) { return fmaxf(x, 0.0f); }

// ---------------------------------------------------------------------------
// Accurate sin/cos (flag-independent): Cody-Waite in double + Cephes fp32
// ---------------------------------------------------------------------------
__device__ __forceinline__ float trig_eval(float x, int cos_flag) {
    double d  = (double)x * 0.63661977236758134308;
    int    ki = __double2int_rn(d);
    float  rf = (float)((double)x - (double)ki * 1.57079632679489661923);
    int    q  = (ki + cos_flag) & 3;
    float  z  = rf * rf;
    float s = ((-1.9515295891e-4f * z + 8.3321608736e-3f) * z - 1.6666654611e-1f)
                  * z * rf + rf;
    float c = ((2.443315711809948e-5f * z - 1.388731625493765e-3f) * z
                  + 4.166664568298827e-2f) * z * z - 0.5f * z + 1.0f;
    float res = (q & 1) ? c : s;
    return (q & 2) ? -res : res;
}

// ---------------------------------------------------------------------------
// Prep (single launch, 1537 blocks):
//   [0,1024):    Ax / Ay tables
//   [1024,1536): W2 -> fp16 fragment-major (uint4 per lane covers 2 n8-tiles)
//   1536:        time branch -> g_b1eff
//
// W2H packing for element (n, k), value W2f[k*512+n]:
//   k16=k>>4, lane=(n&7)*4+((k&7)>>1), reg=(k>>3)&1, np=(n>>4), o=(n>>3)&1
//   uint4 index = (k16*32 + np)*32 + lane,  component = o*2 + reg
//   packed half pair = (k even, k odd)
// ---------------------------------------------------------------------------
__global__ void nivr_prep_kernel(const float* __restrict__ W1p,
                                 const float* __restrict__ b1p,
                                 const float* __restrict__ W2p,
                                 const float* __restrict__ b2p,
                                 const float* __restrict__ W1f,
                                 const float* __restrict__ b1f,
                                 const float* __restrict__ W2f,
                                 const int*   __restrict__ idx_p) {
    const int b = blockIdx.x, tid = threadIdx.x;
    if (b < 1024) {
        const int axis = b >> 9;
        const int c    = b & 511;
        __shared__ float pe[20];
        if (tid < 20) {
            int l = tid % 10;
            float ang = (((float)c * (1.0f / 512.0f)) * (float)(1 << l))
                            * 3.14159265358979323846f;
            pe[tid] = trig_eval(ang, tid >= 10);
        }
        __syncthreads();
        const float* Wr  = W1f + axis * 20 * 512;
        float*       dst = (axis ? g_Ay : g_Ax) + c * 512;
        for (int j = tid; j < 512; j += NTHR) {
            float acc = 0.0f;
            #pragma unroll
            for (int f = 0; f < 20; f++)
                acc = fmaf(pe[f], Wr[f * 512 + j], acc);
            dst[j] = acc;
        }
    } else if (b < 1536) {
        const int n  = b - 1024;
        const int k  = tid * 2;             // even k; pack (k, k+1)
        float lo = W2f[(size_t)k * 512 + n];
        float hi = W2f[(size_t)(k + 1) * 512 + n];
        int k16  = k >> 4;
        int lane = (n & 7) * 4 + ((k & 7) >> 1);
        int reg  = (k >> 3) & 1;
        int idx4 = (k16 * 32 + (n >> 4)) * 32 + lane;
        int comp = ((n >> 3) & 1) * 2 + reg;
        g_W2H[idx4 * 4 + comp] = h2u(lo, hi);
    } else {
        __shared__ float sr[32];
        __shared__ float sh[256];
        __shared__ float sphi[128];
        float t = (float)(*idx_p) / 300.0f;
        if (tid < 32) {
            int l = tid & 15;
            float ang = (t * (float)(1 << l)) * 3.14159265358979323846f;
            sr[tid] = trig_eval(ang, tid >= 16);
        }
        __syncthreads();
        {
            float acc = b1p[tid];
            #pragma unroll
            for (int k = 0; k < 32; k++)
                acc = fmaf(sr[k], W1p[k * 256 + tid], acc);
            sh[tid] = fmaxf(acc, 0.0f);
        }
        __syncthreads();
        if (tid < 128) {
            float acc = b2p[tid];
            #pragma unroll 4
            for (int k = 0; k < 256; k++)
                acc = fmaf(sh[k], W2p[k * 128 + tid], acc);
            sphi[tid] = acc;
        }
        __syncthreads();
        for (int j = tid; j < 512; j += NTHR) {
            float acc = b1f[j];
            #pragma unroll 4
            for (int k = 0; k < 128; k++)
                acc = fmaf(sphi[k], W1f[(40 + k) * 512 + j], acc);
            g_b1eff[j] = acc;
        }
    }
}

// ---------------------------------------------------------------------------
// Main: CTA = 64 pixels, 8 warps all along N (warp tile m64 x n64).
// Full A (64x512 fp16 fragments, 64KB) produced into smem up front: ONE sync,
// then 32 barrier-free k16 MMA steps with register-double-buffered B from L2.
// ---------------------------------------------------------------------------
#define SA_U4    4096                      /* 32kt x 4mt x 32lane uint4 = 64KB */
#define OFF_SA   0
#define OFF_B1   (SA_U4 * 16)              /* 65536 */
#define OFF_B2   (OFF_B1 + 2048)
#define OFF_W3   (OFF_B2 + 2048)
#define OFF_PART (OFF_W3 + 6144)
#define OFF_XY   (OFF_PART + 8 * 64 * 3 * 4)
#define SMEM_TOT (OFF_XY + 512)

__global__ __launch_bounds__(NTHR)
void nivr_mma_kernel(const float* __restrict__ coords,
                     const float* __restrict__ b2f,
                     const float* __restrict__ W3f,
                     const float* __restrict__ b3f,
                     float* __restrict__ out) {
    extern __shared__ char smem[];
    uint4* sA4   = (uint4*)(smem + OFF_SA);
    float* sB1   = (float*)(smem + OFF_B1);
    float* sB2   = (float*)(smem + OFF_B2);
    float* sW3   = (float*)(smem + OFF_W3);
    float* sPart = (float*)(smem + OFF_PART);   // [8][64][3]
    int*   sX    = (int*)(smem + OFF_XY);
    int*   sY    = sX + 64;

    const int tid  = threadIdx.x;
    const int wid  = tid >> 5;            // warpN: 0..7 (cols wid*64..+63)
    const int lane = tid & 31;
    const int g    = lane >> 2;
    const int tg   = lane & 3;
    const int pix0 = blockIdx.x * 64;

    if (tid < 64) {
        sX[tid] = (int)coords[(pix0 + tid) * 2 + 0];
        sY[tid] = (int)coords[(pix0 + tid) * 2 + 1];
    }
    for (int i = tid; i < 512;  i += NTHR) { sB1[i] = g_b1eff[i]; sB2[i] = b2f[i]; }
    for (int i = tid; i < 1536; i += NTHR) sW3[i] = W3f[i];
    __syncthreads();

    // ---- produce full A into smem (fragment layout: [kt][mt][lane]) -------
    {
        const int pkt = tid >> 7;          // k16 parity within 32-chunk
        const int pmt = (tid >> 5) & 3;
        const int pln = tid & 31;
        const int pg  = pln >> 2, ptg = pln & 3;
        const int p0  = pmt * 16 + pg, p1 = p0 + 8;
        const float* ax0 = g_Ax + (size_t)sX[p0] * 512;
        const float* ay0 = g_Ay + (size_t)sY[p0] * 512;
        const float* ax1 = g_Ax + (size_t)sX[p1] * 512;
        const float* ay1 = g_Ay + (size_t)sY[p1] * 512;
        const int koff = pkt * 16 + ptg * 2;
        const int slot = (pkt * 4 + pmt) * 32 + pln;
        #pragma unroll 4
        for (int kc = 0; kc < 16; kc++) {
            const int kb = kc * 32 + koff;
            float2 xa = *(const float2*)(ax0 + kb),     ya = *(const float2*)(ay0 + kb);
            float2 xb = *(const float2*)(ax0 + kb + 8), yb = *(const float2*)(ay0 + kb + 8);
            float2 xc = *(const float2*)(ax1 + kb),     yc = *(const float2*)(ay1 + kb);
            float2 xd = *(const float2*)(ax1 + kb + 8), yd = *(const float2*)(ay1 + kb + 8);
            float2 ba = *(const float2*)(sB1 + kb),     bb = *(const float2*)(sB1 + kb + 8);
            uint4 v;
            v.x = h2u(relu_f(xa.x + ya.x + ba.x), relu_f(xa.y + ya.y + ba.y));
            v.y = h2u(relu_f(xc.x + yc.x + ba.x), relu_f(xc.y + yc.y + ba.y));
            v.z = h2u(relu_f(xb.x + yb.x + bb.x), relu_f(xb.y + yb.y + bb.y));
            v.w = h2u(relu_f(xd.x + yd.x + bb.x), relu_f(xd.y + yd.y + bb.y));
            sA4[kc * 256 + slot] = v;      // frag for kt = kc*2 + pkt
        }
    }
    __syncthreads();

    // ---- 32 barrier-free k16 MMA steps, B double-buffered from L2 ---------
    float acc[4][8][4];
    #pragma unroll
    for (int m = 0; m < 4; m++)
        #pragma unroll
        for (int n = 0; n < 8; n++)
            acc[m][n][0] = acc[m][n][1] = acc[m][n][2] = acc[m][n][3] = 0.0f;

    const uint4* bbase = (const uint4*)g_W2H + wid * 4 * 32 + lane;
    uint4 bcur[4], bnxt[4];
    #pragma unroll
    for (int np = 0; np < 4; np++) bcur[np] = bbase[np * 32];

    #pragma unroll 2
    for (int kt = 0; kt < 32; kt++) {
        if (kt < 31) {
            #pragma unroll
            for (int np = 0; np < 4; np++)
                bnxt[np] = bbase[(kt + 1) * 1024 + np * 32];
        }
        uint4 af[4];
        #pragma unroll
        for (int m = 0; m < 4; m++)
            af[m] = sA4[kt * 128 + m * 32 + lane];
        #pragma unroll
        for (int np = 0; np < 4; np++) {
            #pragma unroll
            for (int m = 0; m < 4; m++) {
                MMA_F16(acc[m][np * 2 + 0], af[m], bcur[np].x, bcur[np].y);
                MMA_F16(acc[m][np * 2 + 1], af[m], bcur[np].z, bcur[np].w);
            }
        }
        #pragma unroll
        for (int np = 0; np < 4; np++) bcur[np] = bnxt[np];
    }

    // ---- epilogue: relu+bias, fold layer-3 into rgb partials ---------------
    float rp[8][3];
    #pragma unroll
    for (int i = 0; i < 8; i++) rp[i][0] = rp[i][1] = rp[i][2] = 0.0f;

    #pragma unroll
    for (int m = 0; m < 4; m++)
        #pragma unroll
        for (int nt = 0; nt < 8; nt++) {
            int c0 = wid * 64 + nt * 8 + tg * 2;
            float h0 = relu_f(acc[m][nt][0] + sB2[c0]);
            float h1 = relu_f(acc[m][nt][1] + sB2[c0 + 1]);
            float h2 = relu_f(acc[m][nt][2] + sB2[c0]);
            float h3 = relu_f(acc[m][nt][3] + sB2[c0 + 1]);
            #pragma unroll
            for (int ch = 0; ch < 3; ch++) {
                float w0 = sW3[c0 * 3 + ch], w1 = sW3[(c0 + 1) * 3 + ch];
                rp[m * 2 + 0][ch] = fmaf(h0, w0, fmaf(h1, w1, rp[m * 2 + 0][ch]));
                rp[m * 2 + 1][ch] = fmaf(h2, w0, fmaf(h3, w1, rp[m * 2 + 1][ch]));
            }
        }

    #pragma unroll
    for (int i = 0; i < 8; i++)
        #pragma unroll
        for (int ch = 0; ch < 3; ch++) {
            rp[i][ch] += __shfl_xor_sync(0xffffffffu, rp[i][ch], 1);
            rp[i][ch] += __shfl_xor_sync(0xffffffffu, rp[i][ch], 2);
        }
    if (tg == 0) {
        #pragma unroll
        for (int m = 0; m < 4; m++)
            #pragma unroll
            for (int rh = 0; rh < 2; rh++) {
                int row = m * 16 + rh * 8 + g;
                #pragma unroll
                for (int ch = 0; ch < 3; ch++)
                    sPart[(wid * 64 + row) * 3 + ch] = rp[m * 2 + rh][ch];
            }
    }
    __syncthreads();
    if (tid < 64) {
        #pragma unroll
        for (int ch = 0; ch < 3; ch++) {
            float s = b3f[ch];
            #pragma unroll
            for (int w = 0; w < 8; w++) s += sPart[(w * 64 + tid) * 3 + ch];
            out[ch * N_PIX + pix0 + tid] = s;
        }
    }
}

// ---------------------------------------------------------------------------
extern "C" void kernel_launch(void* const* d_in, const int* in_sizes, int n_in,
                              void* d_out, int out_size) {
    const float* coords = (const float*)d_in[0];
    const float* W1p    = (const float*)d_in[1];
    const float* b1p    = (const float*)d_in[2];
    const float* W2p    = (const float*)d_in[3];
    const float* b2p    = (const float*)d_in[4];
    const float* W1f    = (const float*)d_in[5];
    const float* b1f    = (const float*)d_in[6];
    const float* W2f    = (const float*)d_in[7];
    const float* b2f    = (const float*)d_in[8];
    const float* W3f    = (const float*)d_in[9];
    const float* b3f    = (const float*)d_in[10];
    const int*   idx    = (const int*)d_in[11];
    float*       out    = (float*)d_out;

    cudaFuncSetAttribute(nivr_mma_kernel,
                         cudaFuncAttributeMaxDynamicSharedMemorySize, SMEM_TOT);

    nivr_prep_kernel<<<1537, NTHR>>>(W1p, b1p, W2p, b2p, W1f, b1f, W2f, idx);
    nivr_mma_kernel<<<N_PIX / 64, NTHR, SMEM_TOT>>>(coords, b2f, W3f, b3f, out);
}

// round 9
// speedup vs baseline: 7.6251x; 1.1200x over previous
#include <cuda_runtime.h>
#include <cuda_fp16.h>
#include <math.h>
#include <stdint.h>

#define N_PIX (512 * 512)
#define NTHR  256

// ---------------------------------------------------------------------------
// Device scratch (no allocations allowed)
// ---------------------------------------------------------------------------
__device__ float    g_b1eff[512];        // b1f + phi_t @ W1f[40:,:]
__device__ float    g_Ax[512 * 512];     // posenc_x(c) @ W1f[0:20,:]
__device__ float    g_Ay[512 * 512];     // posenc_y(c) @ W1f[20:40,:]
__device__ uint32_t g_W2H[512 * 256];    // W2 fp16, uint4-fragment-major

// m16n8k16 fp16 mma, fp32 acc
#define MMA_F16(d, a, b0, b1)                                                  \
    asm volatile("mma.sync.aligned.m16n8k16.row.col.f32.f16.f16.f32 "          \
                 "{%0,%1,%2,%3},{%4,%5,%6,%7},{%8,%9},{%0,%1,%2,%3};"          \
                 : "+f"((d)[0]), "+f"((d)[1]), "+f"((d)[2]), "+f"((d)[3])      \
                 : "r"((a).x), "r"((a).y), "r"((a).z), "r"((a).w),             \
                   "r"(b0), "r"(b1))

__device__ __forceinline__ uint32_t h2u(float a, float b) {
    __half2 h = __floats2half2_rn(a, b);
    return *(uint32_t*)&h;
}
__device__ __forceinline__ float relu_f(float x) { return fmaxf(x, 0.0f); }

// ---------------------------------------------------------------------------
// Accurate sin/cos (flag-independent): Cody-Waite in double + Cephes fp32
// ---------------------------------------------------------------------------
__device__ __forceinline__ float trig_eval(float x, int cos_flag) {
    double d  = (double)x * 0.63661977236758134308;
    int    ki = __double2int_rn(d);
    float  rf = (float)((double)x - (double)ki * 1.57079632679489661923);
    int    q  = (ki + cos_flag) & 3;
    float  z  = rf * rf;
    float s = ((-1.9515295891e-4f * z + 8.3321608736e-3f) * z - 1.6666654611e-1f)
                  * z * rf + rf;
    float c = ((2.443315711809948e-5f * z - 1.388731625493765e-3f) * z
                  + 4.166664568298827e-2f) * z * z - 0.5f * z + 1.0f;
    float res = (q & 1) ? c : s;
    return (q & 2) ? -res : res;
}

// ---------------------------------------------------------------------------
// Prep (single launch, 1537 blocks):
//   [0,1024):    Ax / Ay tables
//   [1024,1536): W2 -> fp16 fragment-major (uint4 per lane covers 2 n8-tiles)
//   1536:        time branch -> g_b1eff
//
// W2H packing for element (n, k), value W2f[k*512+n]:
//   k16=k>>4, lane=(n&7)*4+((k&7)>>1), reg=(k>>3)&1, np=(n>>4), o=(n>>3)&1
//   uint4 index = (k16*32 + np)*32 + lane,  component = o*2 + reg
//   packed half pair = (k even, k odd)
// ---------------------------------------------------------------------------
__global__ void nivr_prep_kernel(const float* __restrict__ W1p,
                                 const float* __restrict__ b1p,
                                 const float* __restrict__ W2p,
                                 const float* __restrict__ b2p,
                                 const float* __restrict__ W1f,
                                 const float* __restrict__ b1f,
                                 const float* __restrict__ W2f,
                                 const int*   __restrict__ idx_p) {
    const int b = blockIdx.x, tid = threadIdx.x;
    if (b < 1024) {
        const int axis = b >> 9;
        const int c    = b & 511;
        __shared__ float pe[20];
        if (tid < 20) {
            int l = tid % 10;
            float ang = (((float)c * (1.0f / 512.0f)) * (float)(1 << l))
                            * 3.14159265358979323846f;
            pe[tid] = trig_eval(ang, tid >= 10);
        }
        __syncthreads();
        const float* Wr  = W1f + axis * 20 * 512;
        float*       dst = (axis ? g_Ay : g_Ax) + c * 512;
        for (int j = tid; j < 512; j += NTHR) {
            float acc = 0.0f;
            #pragma unroll
            for (int f = 0; f < 20; f++)
                acc = fmaf(pe[f], Wr[f * 512 + j], acc);
            dst[j] = acc;
        }
    } else if (b < 1536) {
        const int n  = b - 1024;
        const int k  = tid * 2;             // even k; pack (k, k+1)
        float lo = W2f[(size_t)k * 512 + n];
        float hi = W2f[(size_t)(k + 1) * 512 + n];
        int k16  = k >> 4;
        int lane = (n & 7) * 4 + ((k & 7) >> 1);
        int reg  = (k >> 3) & 1;
        int idx4 = (k16 * 32 + (n >> 4)) * 32 + lane;
        int comp = ((n >> 3) & 1) * 2 + reg;
        g_W2H[idx4 * 4 + comp] = h2u(lo, hi);
    } else {
        __shared__ float sr[32];
        __shared__ float sh[256];
        __shared__ float sphi[128];
        float t = (float)(*idx_p) / 300.0f;
        if (tid < 32) {
            int l = tid & 15;
            float ang = (t * (float)(1 << l)) * 3.14159265358979323846f;
            sr[tid] = trig_eval(ang, tid >= 16);
        }
        __syncthreads();
        {
            float acc = b1p[tid];
            #pragma unroll
            for (int k = 0; k < 32; k++)
                acc = fmaf(sr[k], W1p[k * 256 + tid], acc);
            sh[tid] = fmaxf(acc, 0.0f);
        }
        __syncthreads();
        if (tid < 128) {
            float acc = b2p[tid];
            #pragma unroll 4
            for (int k = 0; k < 256; k++)
                acc = fmaf(sh[k], W2p[k * 128 + tid], acc);
            sphi[tid] = acc;
        }
        __syncthreads();
        for (int j = tid; j < 512; j += NTHR) {
            float acc = b1f[j];
            #pragma unroll 4
            for (int k = 0; k < 128; k++)
                acc = fmaf(sphi[k], W1f[(40 + k) * 512 + j], acc);
            g_b1eff[j] = acc;
        }
    }
}

// ---------------------------------------------------------------------------
// Main: CTA = 64 pixels, 8 warps all along N (warp tile m64 x n64).
// Full A (64x512 fp16 fragments, 64KB) in smem up front (ONE sync), then 32
// barrier-free k16 MMA steps; B triple-buffered in registers, prefetch
// distance 2 kt-steps (~64 MMA issues) to cover L2 latency.
// ---------------------------------------------------------------------------
#define SA_U4    4096                      /* 32kt x 4mt x 32lane uint4 = 64KB */
#define OFF_SA   0
#define OFF_B1   (SA_U4 * 16)              /* 65536 */
#define OFF_B2   (OFF_B1 + 2048)
#define OFF_W3   (OFF_B2 + 2048)
#define OFF_PART (OFF_W3 + 6144)
#define OFF_XY   (OFF_PART + 8 * 64 * 3 * 4)
#define SMEM_TOT (OFF_XY + 512)

__global__ __launch_bounds__(NTHR)
void nivr_mma_kernel(const float* __restrict__ coords,
                     const float* __restrict__ b2f,
                     const float* __restrict__ W3f,
                     const float* __restrict__ b3f,
                     float* __restrict__ out) {
    extern __shared__ char smem[];
    uint4* sA4   = (uint4*)(smem + OFF_SA);
    float* sB1   = (float*)(smem + OFF_B1);
    float* sB2   = (float*)(smem + OFF_B2);
    float* sW3   = (float*)(smem + OFF_W3);
    float* sPart = (float*)(smem + OFF_PART);   // [8][64][3]
    int*   sX    = (int*)(smem + OFF_XY);
    int*   sY    = sX + 64;

    const int tid  = threadIdx.x;
    const int wid  = tid >> 5;            // warpN: 0..7 (cols wid*64..+63)
    const int lane = tid & 31;
    const int g    = lane >> 2;
    const int tg   = lane & 3;
    const int pix0 = blockIdx.x * 64;

    if (tid < 64) {
        sX[tid] = (int)coords[(pix0 + tid) * 2 + 0];
        sY[tid] = (int)coords[(pix0 + tid) * 2 + 1];
    }
    for (int i = tid; i < 512;  i += NTHR) { sB1[i] = g_b1eff[i]; sB2[i] = b2f[i]; }
    for (int i = tid; i < 1536; i += NTHR) sW3[i] = W3f[i];
    __syncthreads();

    // ---- produce full A into smem (fragment layout: [kt][mt][lane]) -------
    {
        const int pkt = tid >> 7;          // k16 parity within 32-chunk
        const int pmt = (tid >> 5) & 3;
        const int pln = tid & 31;
        const int pg  = pln >> 2, ptg = pln & 3;
        const int p0  = pmt * 16 + pg, p1 = p0 + 8;
        const float* ax0 = g_Ax + (size_t)sX[p0] * 512;
        const float* ay0 = g_Ay + (size_t)sY[p0] * 512;
        const float* ax1 = g_Ax + (size_t)sX[p1] * 512;
        const float* ay1 = g_Ay + (size_t)sY[p1] * 512;
        const int koff = pkt * 16 + ptg * 2;
        const int slot = (pkt * 4 + pmt) * 32 + pln;
        #pragma unroll 4
        for (int kc = 0; kc < 16; kc++) {
            const int kb = kc * 32 + koff;
            float2 xa = *(const float2*)(ax0 + kb),     ya = *(const float2*)(ay0 + kb);
            float2 xb = *(const float2*)(ax0 + kb + 8), yb = *(const float2*)(ay0 + kb + 8);
            float2 xc = *(const float2*)(ax1 + kb),     yc = *(const float2*)(ay1 + kb);
            float2 xd = *(const float2*)(ax1 + kb + 8), yd = *(const float2*)(ay1 + kb + 8);
            float2 ba = *(const float2*)(sB1 + kb),     bb = *(const float2*)(sB1 + kb + 8);
            uint4 v;
            v.x = h2u(relu_f(xa.x + ya.x + ba.x), relu_f(xa.y + ya.y + ba.y));
            v.y = h2u(relu_f(xc.x + yc.x + ba.x), relu_f(xc.y + yc.y + ba.y));
            v.z = h2u(relu_f(xb.x + yb.x + bb.x), relu_f(xb.y + yb.y + bb.y));
            v.w = h2u(relu_f(xd.x + yd.x + bb.x), relu_f(xd.y + yd.y + bb.y));
            sA4[kc * 256 + slot] = v;      // frag for kt = kc*2 + pkt
        }
    }
    __syncthreads();

    // ---- 32 barrier-free k16 MMA steps, B triple-buffered (distance 2) ----
    float acc[4][8][4];
    #pragma unroll
    for (int m = 0; m < 4; m++)
        #pragma unroll
        for (int n = 0; n < 8; n++)
            acc[m][n][0] = acc[m][n][1] = acc[m][n][2] = acc[m][n][3] = 0.0f;

    const uint4* bbase = (const uint4*)g_W2H + wid * 4 * 32 + lane;
    uint4 bb0[4], bb1[4], bb2[4];
    #pragma unroll
    for (int np = 0; np < 4; np++) {
        bb0[np] = bbase[np * 32];                 // B[kt=0]
        bb1[np] = bbase[1024 + np * 32];          // B[kt=1]
    }

    // One k16-step: prefetch B[KT+2] into LD, MMA with USE.
#define KSTEP_LD(USE, LD, KT)                                                  \
    {                                                                          \
        _Pragma("unroll")                                                      \
        for (int np = 0; np < 4; np++)                                         \
            LD[np] = bbase[((KT) + 2) * 1024 + np * 32];                       \
        uint4 af[4];                                                           \
        _Pragma("unroll")                                                      \
        for (int m = 0; m < 4; m++)                                            \
            af[m] = sA4[(KT) * 128 + m * 32 + lane];                           \
        _Pragma("unroll")                                                      \
        for (int np = 0; np < 4; np++)                                         \
            _Pragma("unroll")                                                  \
            for (int m = 0; m < 4; m++) {                                      \
                MMA_F16(acc[m][np * 2 + 0], af[m], USE[np].x, USE[np].y);      \
                MMA_F16(acc[m][np * 2 + 1], af[m], USE[np].z, USE[np].w);      \
            }                                                                  \
    }
#define KSTEP_NOLD(USE, KT)                                                    \
    {                                                                          \
        uint4 af[4];                                                           \
        _Pragma("unroll")                                                      \
        for (int m = 0; m < 4; m++)                                            \
            af[m] = sA4[(KT) * 128 + m * 32 + lane];                           \
        _Pragma("unroll")                                                      \
        for (int np = 0; np < 4; np++)                                         \
            _Pragma("unroll")                                                  \
            for (int m = 0; m < 4; m++) {                                      \
                MMA_F16(acc[m][np * 2 + 0], af[m], USE[np].x, USE[np].y);      \
                MMA_F16(acc[m][np * 2 + 1], af[m], USE[np].z, USE[np].w);      \
            }                                                                  \
    }

    // rotation: B[j] lives in bb[j % 3]
    #pragma unroll 1
    for (int kt = 0; kt < 30; kt += 3) {
        KSTEP_LD(bb0, bb2, kt);        // use B[kt]   (kt%3==0), load B[kt+2]
        KSTEP_LD(bb1, bb0, kt + 1);    // use B[kt+1],            load B[kt+3]
        KSTEP_LD(bb2, bb1, kt + 2);    // use B[kt+2],            load B[kt+4]
    }
    KSTEP_NOLD(bb0, 30);
    KSTEP_NOLD(bb1, 31);

    // ---- epilogue: relu+bias, fold layer-3 into rgb partials ---------------
    float rp[8][3];
    #pragma unroll
    for (int i = 0; i < 8; i++) rp[i][0] = rp[i][1] = rp[i][2] = 0.0f;

    #pragma unroll
    for (int m = 0; m < 4; m++)
        #pragma unroll
        for (int nt = 0; nt < 8; nt++) {
            int c0 = wid * 64 + nt * 8 + tg * 2;
            float h0 = relu_f(acc[m][nt][0] + sB2[c0]);
            float h1 = relu_f(acc[m][nt][1] + sB2[c0 + 1]);
            float h2 = relu_f(acc[m][nt][2] + sB2[c0]);
            float h3 = relu_f(acc[m][nt][3] + sB2[c0 + 1]);
            #pragma unroll
            for (int ch = 0; ch < 3; ch++) {
                float w0 = sW3[c0 * 3 + ch], w1 = sW3[(c0 + 1) * 3 + ch];
                rp[m * 2 + 0][ch] = fmaf(h0, w0, fmaf(h1, w1, rp[m * 2 + 0][ch]));
                rp[m * 2 + 1][ch] = fmaf(h2, w0, fmaf(h3, w1, rp[m * 2 + 1][ch]));
            }
        }

    #pragma unroll
    for (int i = 0; i < 8; i++)
        #pragma unroll
        for (int ch = 0; ch < 3; ch++) {
            rp[i][ch] += __shfl_xor_sync(0xffffffffu, rp[i][ch], 1);
            rp[i][ch] += __shfl_xor_sync(0xffffffffu, rp[i][ch], 2);
        }
    if (tg == 0) {
        #pragma unroll
        for (int m = 0; m < 4; m++)
            #pragma unroll
            for (int rh = 0; rh < 2; rh++) {
                int row = m * 16 + rh * 8 + g;
                #pragma unroll
                for (int ch = 0; ch < 3; ch++)
                    sPart[(wid * 64 + row) * 3 + ch] = rp[m * 2 + rh][ch];
            }
    }
    __syncthreads();
    if (tid < 64) {
        #pragma unroll
        for (int ch = 0; ch < 3; ch++) {
            float s = b3f[ch];
            #pragma unroll
            for (int w = 0; w < 8; w++) s += sPart[(w * 64 + tid) * 3 + ch];
            out[ch * N_PIX + pix0 + tid] = s;
        }
    }
}

// ---------------------------------------------------------------------------
extern "C" void kernel_launch(void* const* d_in, const int* in_sizes, int n_in,
                              void* d_out, int out_size) {
    const float* coords = (const float*)d_in[0];
    const float* W1p    = (const float*)d_in[1];
    const float* b1p    = (const float*)d_in[2];
    const float* W2p    = (const float*)d_in[3];
    const float* b2p    = (const float*)d_in[4];
    const float* W1f    = (const float*)d_in[5];
    const float* b1f    = (const float*)d_in[6];
    const float* W2f    = (const float*)d_in[7];
    const float* b2f    = (const float*)d_in[8];
    const float* W3f    = (const float*)d_in[9];
    const float* b3f    = (const float*)d_in[10];
    const int*   idx    = (const int*)d_in[11];
    float*       out    = (float*)d_out;

    cudaFuncSetAttribute(nivr_mma_kernel,
                         cudaFuncAttributeMaxDynamicSharedMemorySize, SMEM_TOT);

    nivr_prep_kernel<<<1537, NTHR>>>(W1p, b1p, W2p, b2p, W1f, b1f, W2f, idx);
    nivr_mma_kernel<<<N_PIX / 64, NTHR, SMEM_TOT>>>(coords, b2f, W3f, b3f, out);
}

// round 10
// speedup vs baseline: 7.8632x; 1.0312x over previous
#include <cuda_runtime.h>
#include <cuda_fp16.h>
#include <math.h>
#include <stdint.h>

#define N_PIX (512 * 512)
#define NTHR  256
#define MTHR  512

// ---------------------------------------------------------------------------
// Device scratch (no allocations allowed)
// ---------------------------------------------------------------------------
__device__ float    g_b1eff[512];        // b1f + phi_t @ W1f[40:,:]
__device__ float    g_Ax[512 * 512];     // posenc_x(c) @ W1f[0:20,:]
__device__ float    g_Ay[512 * 512];     // posenc_y(c) @ W1f[20:40,:]
__device__ uint32_t g_W2H[512 * 256];    // W2 fp16, uint4-fragment-major

// m16n8k16 fp16 mma, fp32 acc
#define MMA_F16(d, a, b0, b1)                                                  \
    asm volatile("mma.sync.aligned.m16n8k16.row.col.f32.f16.f16.f32 "          \
                 "{%0,%1,%2,%3},{%4,%5,%6,%7},{%8,%9},{%0,%1,%2,%3};"          \
                 : "+f"((d)[0]), "+f"((d)[1]), "+f"((d)[2]), "+f"((d)[3])      \
                 : "r"((a).x), "r"((a).y), "r"((a).z), "r"((a).w),             \
                   "r"(b0), "r"(b1))

__device__ __forceinline__ uint32_t h2u(float a, float b) {
    __half2 h = __floats2half2_rn(a, b);
    return *(uint32_t*)&h;
}
__device__ __forceinline__ float relu_f(float x) { return fmaxf(x, 0.0f); }

// ---------------------------------------------------------------------------
// Accurate sin/cos (flag-independent): Cody-Waite in double + Cephes fp32
// ---------------------------------------------------------------------------
__device__ __forceinline__ float trig_eval(float x, int cos_flag) {
    double d  = (double)x * 0.63661977236758134308;
    int    ki = __double2int_rn(d);
    float  rf = (float)((double)x - (double)ki * 1.57079632679489661923);
    int    q  = (ki + cos_flag) & 3;
    float  z  = rf * rf;
    float s = ((-1.9515295891e-4f * z + 8.3321608736e-3f) * z - 1.6666654611e-1f)
                  * z * rf + rf;
    float c = ((2.443315711809948e-5f * z - 1.388731625493765e-3f) * z
                  + 4.166664568298827e-2f) * z * z - 0.5f * z + 1.0f;
    float res = (q & 1) ? c : s;
    return (q & 2) ? -res : res;
}

// ---------------------------------------------------------------------------
// Prep (single launch, 1537 blocks):
//   [0,1024):    Ax / Ay tables
//   [1024,1536): W2 -> fp16 fragment-major (uint4 per lane covers 2 n8-tiles)
//   1536:        time branch -> g_b1eff
//
// W2H packing for element (n, k), value W2f[k*512+n]:
//   k16=k>>4, lane=(n&7)*4+((k&7)>>1), reg=(k>>3)&1, np=(n>>4), o=(n>>3)&1
//   uint4 index = (k16*32 + np)*32 + lane,  component = o*2 + reg
//   packed half pair = (k even, k odd)
// ---------------------------------------------------------------------------
__global__ void nivr_prep_kernel(const float* __restrict__ W1p,
                                 const float* __restrict__ b1p,
                                 const float* __restrict__ W2p,
                                 const float* __restrict__ b2p,
                                 const float* __restrict__ W1f,
                                 const float* __restrict__ b1f,
                                 const float* __restrict__ W2f,
                                 const int*   __restrict__ idx_p) {
    const int b = blockIdx.x, tid = threadIdx.x;
    if (b < 1024) {
        const int axis = b >> 9;
        const int c    = b & 511;
        __shared__ float pe[20];
        if (tid < 20) {
            int l = tid % 10;
            float ang = (((float)c * (1.0f / 512.0f)) * (float)(1 << l))
                            * 3.14159265358979323846f;
            pe[tid] = trig_eval(ang, tid >= 10);
        }
        __syncthreads();
        const float* Wr  = W1f + axis * 20 * 512;
        float*       dst = (axis ? g_Ay : g_Ax) + c * 512;
        for (int j = tid; j < 512; j += NTHR) {
            float acc = 0.0f;
            #pragma unroll
            for (int f = 0; f < 20; f++)
                acc = fmaf(pe[f], Wr[f * 512 + j], acc);
            dst[j] = acc;
        }
    } else if (b < 1536) {
        const int n  = b - 1024;
        const int k  = tid * 2;             // even k; pack (k, k+1)
        float lo = W2f[(size_t)k * 512 + n];
        float hi = W2f[(size_t)(k + 1) * 512 + n];
        int k16  = k >> 4;
        int lane = (n & 7) * 4 + ((k & 7) >> 1);
        int reg  = (k >> 3) & 1;
        int idx4 = (k16 * 32 + (n >> 4)) * 32 + lane;
        int comp = ((n >> 3) & 1) * 2 + reg;
        g_W2H[idx4 * 4 + comp] = h2u(lo, hi);
    } else {
        __shared__ float sr[32];
        __shared__ float sh[256];
        __shared__ float sphi[128];
        float t = (float)(*idx_p) / 300.0f;
        if (tid < 32) {
            int l = tid & 15;
            float ang = (t * (float)(1 << l)) * 3.14159265358979323846f;
            sr[tid] = trig_eval(ang, tid >= 16);
        }
        __syncthreads();
        {
            float acc = b1p[tid];
            #pragma unroll
            for (int k = 0; k < 32; k++)
                acc = fmaf(sr[k], W1p[k * 256 + tid], acc);
            sh[tid] = fmaxf(acc, 0.0f);
        }
        __syncthreads();
        if (tid < 128) {
            float acc = b2p[tid];
            #pragma unroll 4
            for (int k = 0; k < 256; k++)
                acc = fmaf(sh[k], W2p[k * 128 + tid], acc);
            sphi[tid] = acc;
        }
        __syncthreads();
        for (int j = tid; j < 512; j += NTHR) {
            float acc = b1f[j];
            #pragma unroll 4
            for (int k = 0; k < 128; k++)
                acc = fmaf(sphi[k], W1f[(40 + k) * 512 + j], acc);
            g_b1eff[j] = acc;
        }
    }
}

// ---------------------------------------------------------------------------
// Main: CTA = 64 pixels, 512 threads / 16 warps, each warp n32 (4 n8-tiles).
// Full A (64x512 fp16 fragments, 64KB) in smem up front (ONE sync), then 32
// barrier-free k16 MMA steps; B triple-buffered in regs, prefetch distance 2.
// 4 warps/SMSP for latency hiding; B read once per CTA (disjoint n-columns).
// ---------------------------------------------------------------------------
#define SA_U4    4096                      /* 32kt x 4mt x 32lane uint4 = 64KB */
#define OFF_SA   0
#define OFF_B1   (SA_U4 * 16)              /* 65536 */
#define OFF_B2   (OFF_B1 + 2048)
#define OFF_W3   (OFF_B2 + 2048)
#define OFF_PART (OFF_W3 + 6144)
#define OFF_XY   (OFF_PART + 16 * 64 * 3 * 4)
#define SMEM_TOT (OFF_XY + 512)

__global__ __launch_bounds__(MTHR)
void nivr_mma_kernel(const float* __restrict__ coords,
                     const float* __restrict__ b2f,
                     const float* __restrict__ W3f,
                     const float* __restrict__ b3f,
                     float* __restrict__ out) {
    extern __shared__ char smem[];
    uint4* sA4   = (uint4*)(smem + OFF_SA);
    float* sB1   = (float*)(smem + OFF_B1);
    float* sB2   = (float*)(smem + OFF_B2);
    float* sW3   = (float*)(smem + OFF_W3);
    float* sPart = (float*)(smem + OFF_PART);   // [16][64][3]
    int*   sX    = (int*)(smem + OFF_XY);
    int*   sY    = sX + 64;

    const int tid  = threadIdx.x;
    const int wid  = tid >> 5;            // warpN: 0..15 (cols wid*32..+31)
    const int lane = tid & 31;
    const int g    = lane >> 2;
    const int tg   = lane & 3;
    const int pix0 = blockIdx.x * 64;

    if (tid < 64) {
        sX[tid] = (int)coords[(pix0 + tid) * 2 + 0];
        sY[tid] = (int)coords[(pix0 + tid) * 2 + 1];
    }
    for (int i = tid; i < 512;  i += MTHR) { sB1[i] = g_b1eff[i]; sB2[i] = b2f[i]; }
    for (int i = tid; i < 1536; i += MTHR) sW3[i] = W3f[i];
    __syncthreads();

    // ---- produce full A into smem (fragment layout: [kt][mt][lane]) -------
    // 512 threads: [pkc2][pkt2][pmt4][lane32]; each handles 8 k-chunks.
    {
        const int pkc = tid >> 8;          // k-chunk parity
        const int pkt = (tid >> 7) & 1;    // k16 parity within 32-chunk
        const int pmt = (tid >> 5) & 3;
        const int pln = tid & 31;
        const int pg  = pln >> 2, ptg = pln & 3;
        const int p0  = pmt * 16 + pg, p1 = p0 + 8;
        const float* ax0 = g_Ax + (size_t)sX[p0] * 512;
        const float* ay0 = g_Ay + (size_t)sY[p0] * 512;
        const float* ax1 = g_Ax + (size_t)sX[p1] * 512;
        const float* ay1 = g_Ay + (size_t)sY[p1] * 512;
        const int koff = pkt * 16 + ptg * 2;
        const int slot = (pkt * 4 + pmt) * 32 + pln;
        #pragma unroll 4
        for (int i = 0; i < 8; i++) {
            const int kc = i * 2 + pkc;
            const int kb = kc * 32 + koff;
            float2 xa = *(const float2*)(ax0 + kb),     ya = *(const float2*)(ay0 + kb);
            float2 xb = *(const float2*)(ax0 + kb + 8), yb = *(const float2*)(ay0 + kb + 8);
            float2 xc = *(const float2*)(ax1 + kb),     yc = *(const float2*)(ay1 + kb);
            float2 xd = *(const float2*)(ax1 + kb + 8), yd = *(const float2*)(ay1 + kb + 8);
            float2 ba = *(const float2*)(sB1 + kb),     bb = *(const float2*)(sB1 + kb + 8);
            uint4 v;
            v.x = h2u(relu_f(xa.x + ya.x + ba.x), relu_f(xa.y + ya.y + ba.y));
            v.y = h2u(relu_f(xc.x + yc.x + ba.x), relu_f(xc.y + yc.y + ba.y));
            v.z = h2u(relu_f(xb.x + yb.x + bb.x), relu_f(xb.y + yb.y + bb.y));
            v.w = h2u(relu_f(xd.x + yd.x + bb.x), relu_f(xd.y + yd.y + bb.y));
            sA4[kc * 256 + slot] = v;      // frag for kt = kc*2 + pkt
        }
    }
    __syncthreads();

    // ---- 32 barrier-free k16 MMA steps, B triple-buffered (distance 2) ----
    float acc[4][4][4];
    #pragma unroll
    for (int m = 0; m < 4; m++)
        #pragma unroll
        for (int n = 0; n < 4; n++)
            acc[m][n][0] = acc[m][n][1] = acc[m][n][2] = acc[m][n][3] = 0.0f;

    // warp wid owns np = wid*2, wid*2+1 (n columns wid*32 .. wid*32+31)
    const uint4* bbase = (const uint4*)g_W2H + wid * 2 * 32 + lane;
    uint4 bb0[2], bb1[2], bb2[2];
    #pragma unroll
    for (int np = 0; np < 2; np++) {
        bb0[np] = bbase[np * 32];                 // B[kt=0]
        bb1[np] = bbase[1024 + np * 32];          // B[kt=1]
    }

    // One k16-step: prefetch B[KT+2] into LD, MMA with USE.
#define KSTEP_LD(USE, LD, KT)                                                  \
    {                                                                          \
        _Pragma("unroll")                                                      \
        for (int np = 0; np < 2; np++)                                         \
            LD[np] = bbase[((KT) + 2) * 1024 + np * 32];                       \
        uint4 af[4];                                                           \
        _Pragma("unroll")                                                      \
        for (int m = 0; m < 4; m++)                                            \
            af[m] = sA4[(KT) * 128 + m * 32 + lane];                           \
        _Pragma("unroll")                                                      \
        for (int np = 0; np < 2; np++)                                         \
            _Pragma("unroll")                                                  \
            for (int m = 0; m < 4; m++) {                                      \
                MMA_F16(acc[m][np * 2 + 0], af[m], USE[np].x, USE[np].y);      \
                MMA_F16(acc[m][np * 2 + 1], af[m], USE[np].z, USE[np].w);      \
            }                                                                  \
    }
#define KSTEP_NOLD(USE, KT)                                                    \
    {                                                                          \
        uint4 af[4];                                                           \
        _Pragma("unroll")                                                      \
        for (int m = 0; m < 4; m++)                                            \
            af[m] = sA4[(KT) * 128 + m * 32 + lane];                           \
        _Pragma("unroll")                                                      \
        for (int np = 0; np < 2; np++)                                         \
            _Pragma("unroll")                                                  \
            for (int m = 0; m < 4; m++) {                                      \
                MMA_F16(acc[m][np * 2 + 0], af[m], USE[np].x, USE[np].y);      \
                MMA_F16(acc[m][np * 2 + 1], af[m], USE[np].z, USE[np].w);      \
            }                                                                  \
    }

    // rotation: B[j] lives in bb[j % 3]
    #pragma unroll 1
    for (int kt = 0; kt < 30; kt += 3) {
        KSTEP_LD(bb0, bb2, kt);
        KSTEP_LD(bb1, bb0, kt + 1);
        KSTEP_LD(bb2, bb1, kt + 2);
    }
    KSTEP_NOLD(bb0, 30);
    KSTEP_NOLD(bb1, 31);

    // ---- epilogue: relu+bias, fold layer-3 into rgb partials ---------------
    float rp[8][3];
    #pragma unroll
    for (int i = 0; i < 8; i++) rp[i][0] = rp[i][1] = rp[i][2] = 0.0f;

    #pragma unroll
    for (int m = 0; m < 4; m++)
        #pragma unroll
        for (int nt = 0; nt < 4; nt++) {
            int c0 = wid * 32 + nt * 8 + tg * 2;
            float h0 = relu_f(acc[m][nt][0] + sB2[c0]);
            float h1 = relu_f(acc[m][nt][1] + sB2[c0 + 1]);
            float h2 = relu_f(acc[m][nt][2] + sB2[c0]);
            float h3 = relu_f(acc[m][nt][3] + sB2[c0 + 1]);
            #pragma unroll
            for (int ch = 0; ch < 3; ch++) {
                float w0 = sW3[c0 * 3 + ch], w1 = sW3[(c0 + 1) * 3 + ch];
                rp[m * 2 + 0][ch] = fmaf(h0, w0, fmaf(h1, w1, rp[m * 2 + 0][ch]));
                rp[m * 2 + 1][ch] = fmaf(h2, w0, fmaf(h3, w1, rp[m * 2 + 1][ch]));
            }
        }

    #pragma unroll
    for (int i = 0; i < 8; i++)
        #pragma unroll
        for (int ch = 0; ch < 3; ch++) {
            rp[i][ch] += __shfl_xor_sync(0xffffffffu, rp[i][ch], 1);
            rp[i][ch] += __shfl_xor_sync(0xffffffffu, rp[i][ch], 2);
        }
    if (tg == 0) {
        #pragma unroll
        for (int m = 0; m < 4; m++)
            #pragma unroll
            for (int rh = 0; rh < 2; rh++) {
                int row = m * 16 + rh * 8 + g;
                #pragma unroll
                for (int ch = 0; ch < 3; ch++)
                    sPart[(wid * 64 + row) * 3 + ch] = rp[m * 2 + rh][ch];
            }
    }
    __syncthreads();
    if (tid < 64) {
        #pragma unroll
        for (int ch = 0; ch < 3; ch++) {
            float s = b3f[ch];
            #pragma unroll
            for (int w = 0; w < 16; w++) s += sPart[(w * 64 + tid) * 3 + ch];
            out[ch * N_PIX + pix0 + tid] = s;
        }
    }
}

// ---------------------------------------------------------------------------
extern "C" void kernel_launch(void* const* d_in, const int* in_sizes, int n_in,
                              void* d_out, int out_size) {
    const float* coords = (const float*)d_in[0];
    const float* W1p    = (const float*)d_in[1];
    const float* b1p    = (const float*)d_in[2];
    const float* W2p    = (const float*)d_in[3];
    const float* b2p    = (const float*)d_in[4];
    const float* W1f    = (const float*)d_in[5];
    const float* b1f    = (const float*)d_in[6];
    const float* W2f    = (const float*)d_in[7];
    const float* b2f    = (const float*)d_in[8];
    const float* W3f    = (const float*)d_in[9];
    const float* b3f    = (const float*)d_in[10];
    const int*   idx    = (const int*)d_in[11];
    float*       out    = (float*)d_out;

    cudaFuncSetAttribute(nivr_mma_kernel,
                         cudaFuncAttributeMaxDynamicSharedMemorySize, SMEM_TOT);

    nivr_prep_kernel<<<1537, NTHR>>>(W1p, b1p, W2p, b2p, W1f, b1f, W2f, idx);
    nivr_mma_kernel<<<N_PIX / 64, MTHR, SMEM_TOT>>>(coords, b2f, W3f, b3f, out);
}

// round 11
// speedup vs baseline: 8.0552x; 1.0244x over previous
#include <cuda_runtime.h>
#include <cuda_fp16.h>
#include <math.h>
#include <stdint.h>

#define N_PIX (512 * 512)
#define NTHR  256
#define MTHR  512

// ---------------------------------------------------------------------------
// Device scratch (no allocations allowed)
// ---------------------------------------------------------------------------
__device__ float    g_b1eff[512];        // b1f + phi_t @ W1f[40:,:]
__device__ float    g_Ax[512 * 512];     // posenc_x(c) @ W1f[0:20,:]
__device__ float    g_Ay[512 * 512];     // posenc_y(c) @ W1f[20:40,:]
__device__ uint32_t g_W2H[512 * 256];    // W2 fp16, uint4-fragment-major

// m16n8k16 fp16 mma, fp32 acc
#define MMA_F16(d, a, b0, b1)                                                  \
    asm volatile("mma.sync.aligned.m16n8k16.row.col.f32.f16.f16.f32 "          \
                 "{%0,%1,%2,%3},{%4,%5,%6,%7},{%8,%9},{%0,%1,%2,%3};"          \
                 : "+f"((d)[0]), "+f"((d)[1]), "+f"((d)[2]), "+f"((d)[3])      \
                 : "r"((a).x), "r"((a).y), "r"((a).z), "r"((a).w),             \
                   "r"(b0), "r"(b1))

__device__ __forceinline__ uint32_t h2u(float a, float b) {
    __half2 h = __floats2half2_rn(a, b);
    return *(uint32_t*)&h;
}
__device__ __forceinline__ float relu_f(float x) { return fmaxf(x, 0.0f); }

// ---------------------------------------------------------------------------
// Accurate sin/cos (flag-independent): Cody-Waite in double + Cephes fp32
// ---------------------------------------------------------------------------
__device__ __forceinline__ float trig_eval(float x, int cos_flag) {
    double d  = (double)x * 0.63661977236758134308;
    int    ki = __double2int_rn(d);
    float  rf = (float)((double)x - (double)ki * 1.57079632679489661923);
    int    q  = (ki + cos_flag) & 3;
    float  z  = rf * rf;
    float s = ((-1.9515295891e-4f * z + 8.3321608736e-3f) * z - 1.6666654611e-1f)
                  * z * rf + rf;
    float c = ((2.443315711809948e-5f * z - 1.388731625493765e-3f) * z
                  + 4.166664568298827e-2f) * z * z - 0.5f * z + 1.0f;
    float res = (q & 1) ? c : s;
    return (q & 2) ? -res : res;
}

// ---------------------------------------------------------------------------
// Prep (single launch, 1537 blocks):
//   [0,1024):    Ax / Ay tables
//   [1024,1536): W2 -> fp16 fragment-major (uint4 per lane covers 2 n8-tiles)
//   1536:        time branch -> g_b1eff
//
// W2H packing for element (n, k), value W2f[k*512+n]:
//   k16=k>>4, lane=(n&7)*4+((k&7)>>1), reg=(k>>3)&1, np=(n>>4), o=(n>>3)&1
//   uint4 index = (k16*32 + np)*32 + lane,  component = o*2 + reg
//   packed half pair = (k even, k odd)
// ---------------------------------------------------------------------------
__global__ void nivr_prep_kernel(const float* __restrict__ W1p,
                                 const float* __restrict__ b1p,
                                 const float* __restrict__ W2p,
                                 const float* __restrict__ b2p,
                                 const float* __restrict__ W1f,
                                 const float* __restrict__ b1f,
                                 const float* __restrict__ W2f,
                                 const int*   __restrict__ idx_p) {
    const int b = blockIdx.x, tid = threadIdx.x;
    if (b < 1024) {
        const int axis = b >> 9;
        const int c    = b & 511;
        __shared__ float pe[20];
        if (tid < 20) {
            int l = tid % 10;
            float ang = (((float)c * (1.0f / 512.0f)) * (float)(1 << l))
                            * 3.14159265358979323846f;
            pe[tid] = trig_eval(ang, tid >= 10);
        }
        __syncthreads();
        const float* Wr  = W1f + axis * 20 * 512;
        float*       dst = (axis ? g_Ay : g_Ax) + c * 512;
        for (int j = tid; j < 512; j += NTHR) {
            float acc = 0.0f;
            #pragma unroll
            for (int f = 0; f < 20; f++)
                acc = fmaf(pe[f], Wr[f * 512 + j], acc);
            dst[j] = acc;
        }
    } else if (b < 1536) {
        const int n  = b - 1024;
        const int k  = tid * 2;             // even k; pack (k, k+1)
        float lo = W2f[(size_t)k * 512 + n];
        float hi = W2f[(size_t)(k + 1) * 512 + n];
        int k16  = k >> 4;
        int lane = (n & 7) * 4 + ((k & 7) >> 1);
        int reg  = (k >> 3) & 1;
        int idx4 = (k16 * 32 + (n >> 4)) * 32 + lane;
        int comp = ((n >> 3) & 1) * 2 + reg;
        g_W2H[idx4 * 4 + comp] = h2u(lo, hi);
    } else {
        __shared__ float sr[32];
        __shared__ float sh[256];
        __shared__ float sphi[128];
        float t = (float)(*idx_p) / 300.0f;
        if (tid < 32) {
            int l = tid & 15;
            float ang = (t * (float)(1 << l)) * 3.14159265358979323846f;
            sr[tid] = trig_eval(ang, tid >= 16);
        }
        __syncthreads();
        {
            float acc = b1p[tid];
            #pragma unroll
            for (int k = 0; k < 32; k++)
                acc = fmaf(sr[k], W1p[k * 256 + tid], acc);
            sh[tid] = fmaxf(acc, 0.0f);
        }
        __syncthreads();
        if (tid < 128) {
            float acc = b2p[tid];
            #pragma unroll 4
            for (int k = 0; k < 256; k++)
                acc = fmaf(sh[k], W2p[k * 128 + tid], acc);
            sphi[tid] = acc;
        }
        __syncthreads();
        for (int j = tid; j < 512; j += NTHR) {
            float acc = b1f[j];
            #pragma unroll 4
            for (int k = 0; k < 128; k++)
                acc = fmaf(sphi[k], W1f[(40 + k) * 512 + j], acc);
            g_b1eff[j] = acc;
        }
    }
}

// ---------------------------------------------------------------------------
// Main: CTA = 64 pixels, 512 threads / 16 warps, each warp n32 (4 n8-tiles).
// Full A (64x512 fp16 fragments, 64KB) in smem up front (ONE sync), then 32
// barrier-free k16 MMA steps; B triple-buffered (distance 2) AND A fragments
// double-buffered (distance 1) in registers -> no same-step load->MMA deps.
// ---------------------------------------------------------------------------
#define SA_U4    4096                      /* 32kt x 4mt x 32lane uint4 = 64KB */
#define OFF_SA   0
#define OFF_B1   (SA_U4 * 16)              /* 65536 */
#define OFF_B2   (OFF_B1 + 2048)
#define OFF_W3   (OFF_B2 + 2048)
#define OFF_PART (OFF_W3 + 6144)
#define OFF_XY   (OFF_PART + 16 * 64 * 3 * 4)
#define SMEM_TOT (OFF_XY + 512)

__global__ __launch_bounds__(MTHR, 1)
void nivr_mma_kernel(const float* __restrict__ coords,
                     const float* __restrict__ b2f,
                     const float* __restrict__ W3f,
                     const float* __restrict__ b3f,
                     float* __restrict__ out) {
    extern __shared__ char smem[];
    uint4* sA4   = (uint4*)(smem + OFF_SA);
    float* sB1   = (float*)(smem + OFF_B1);
    float* sB2   = (float*)(smem + OFF_B2);
    float* sW3   = (float*)(smem + OFF_W3);
    float* sPart = (float*)(smem + OFF_PART);   // [16][64][3]
    int*   sX    = (int*)(smem + OFF_XY);
    int*   sY    = sX + 64;

    const int tid  = threadIdx.x;
    const int wid  = tid >> 5;            // warpN: 0..15 (cols wid*32..+31)
    const int lane = tid & 31;
    const int g    = lane >> 2;
    const int tg   = lane & 3;
    const int pix0 = blockIdx.x * 64;

    if (tid < 64) {
        sX[tid] = (int)coords[(pix0 + tid) * 2 + 0];
        sY[tid] = (int)coords[(pix0 + tid) * 2 + 1];
    }
    for (int i = tid; i < 512;  i += MTHR) { sB1[i] = g_b1eff[i]; sB2[i] = b2f[i]; }
    for (int i = tid; i < 1536; i += MTHR) sW3[i] = W3f[i];
    __syncthreads();

    // ---- produce full A into smem (fragment layout: [kt][mt][lane]) -------
    // 512 threads: [pkc2][pkt2][pmt4][lane32]; each handles 8 k-chunks.
    {
        const int pkc = tid >> 8;          // k-chunk parity
        const int pkt = (tid >> 7) & 1;    // k16 parity within 32-chunk
        const int pmt = (tid >> 5) & 3;
        const int pln = tid & 31;
        const int pg  = pln >> 2, ptg = pln & 3;
        const int p0  = pmt * 16 + pg, p1 = p0 + 8;
        const float* ax0 = g_Ax + (size_t)sX[p0] * 512;
        const float* ay0 = g_Ay + (size_t)sY[p0] * 512;
        const float* ax1 = g_Ax + (size_t)sX[p1] * 512;
        const float* ay1 = g_Ay + (size_t)sY[p1] * 512;
        const int koff = pkt * 16 + ptg * 2;
        const int slot = (pkt * 4 + pmt) * 32 + pln;
        #pragma unroll 4
        for (int i = 0; i < 8; i++) {
            const int kc = i * 2 + pkc;
            const int kb = kc * 32 + koff;
            float2 xa = *(const float2*)(ax0 + kb),     ya = *(const float2*)(ay0 + kb);
            float2 xb = *(const float2*)(ax0 + kb + 8), yb = *(const float2*)(ay0 + kb + 8);
            float2 xc = *(const float2*)(ax1 + kb),     yc = *(const float2*)(ay1 + kb);
            float2 xd = *(const float2*)(ax1 + kb + 8), yd = *(const float2*)(ay1 + kb + 8);
            float2 ba = *(const float2*)(sB1 + kb),     bb = *(const float2*)(sB1 + kb + 8);
            uint4 v;
            v.x = h2u(relu_f(xa.x + ya.x + ba.x), relu_f(xa.y + ya.y + ba.y));
            v.y = h2u(relu_f(xc.x + yc.x + ba.x), relu_f(xc.y + yc.y + ba.y));
            v.z = h2u(relu_f(xb.x + yb.x + bb.x), relu_f(xb.y + yb.y + bb.y));
            v.w = h2u(relu_f(xd.x + yd.x + bb.x), relu_f(xd.y + yd.y + bb.y));
            sA4[kc * 256 + slot] = v;      // frag for kt = kc*2 + pkt
        }
    }
    __syncthreads();

    // ---- 32 barrier-free k16 MMA steps ------------------------------------
    float acc[4][4][4];
    #pragma unroll
    for (int m = 0; m < 4; m++)
        #pragma unroll
        for (int n = 0; n < 4; n++)
            acc[m][n][0] = acc[m][n][1] = acc[m][n][2] = acc[m][n][3] = 0.0f;

    // warp wid owns np = wid*2, wid*2+1 (n columns wid*32 .. wid*32+31)
    const uint4* bbase = (const uint4*)g_W2H + wid * 2 * 32 + lane;
    uint4 bb0[2], bb1[2], bb2[2];        // B[j] lives in bb[j % 3]
    uint4 afA[4], afB[4];                // af[kt] in afA if kt even, afB if odd
    #pragma unroll
    for (int np = 0; np < 2; np++) {
        bb0[np] = bbase[np * 32];                 // B[0]
        bb1[np] = bbase[1024 + np * 32];          // B[1]
    }
    #pragma unroll
    for (int m = 0; m < 4; m++)
        afA[m] = sA4[m * 32 + lane];              // af[0]

    // One k16-step: LDG B[KT+2] -> LDB, LDS af[KT+1] -> LDA, MMA(USEA, USEB)
#define KSTEP_FULL(USEB, LDB, USEA, LDA, KT)                                   \
    {                                                                          \
        _Pragma("unroll")                                                      \
        for (int np = 0; np < 2; np++)                                         \
            LDB[np] = bbase[((KT) + 2) * 1024 + np * 32];                      \
        _Pragma("unroll")                                                      \
        for (int m = 0; m < 4; m++)                                            \
            LDA[m] = sA4[((KT) + 1) * 128 + m * 32 + lane];                    \
        _Pragma("unroll")                                                      \
        for (int np = 0; np < 2; np++)                                         \
            _Pragma("unroll")                                                  \
            for (int m = 0; m < 4; m++) {                                      \
                MMA_F16(acc[m][np * 2 + 0], USEA[m], USEB[np].x, USEB[np].y);  \
                MMA_F16(acc[m][np * 2 + 1], USEA[m], USEB[np].z, USEB[np].w);  \
            }                                                                  \
    }
#define KSTEP_NOB(USEB, USEA, LDA, KT)                                         \
    {                                                                          \
        _Pragma("unroll")                                                      \
        for (int m = 0; m < 4; m++)                                            \
            LDA[m] = sA4[((KT) + 1) * 128 + m * 32 + lane];                    \
        _Pragma("unroll")                                                      \
        for (int np = 0; np < 2; np++)                                         \
            _Pragma("unroll")                                                  \
            for (int m = 0; m < 4; m++) {                                      \
                MMA_F16(acc[m][np * 2 + 0], USEA[m], USEB[np].x, USEB[np].y);  \
                MMA_F16(acc[m][np * 2 + 1], USEA[m], USEB[np].z, USEB[np].w);  \
            }                                                                  \
    }
#define KSTEP_END(USEB, USEA)                                                  \
    {                                                                          \
        _Pragma("unroll")                                                      \
        for (int np = 0; np < 2; np++)                                         \
            _Pragma("unroll")                                                  \
            for (int m = 0; m < 4; m++) {                                      \
                MMA_F16(acc[m][np * 2 + 0], USEA[m], USEB[np].x, USEB[np].y);  \
                MMA_F16(acc[m][np * 2 + 1], USEA[m], USEB[np].z, USEB[np].w);  \
            }                                                                  \
    }

    // 6-step rotation (lcm of B period 3 and af period 2)
    #pragma unroll 1
    for (int kt = 0; kt < 30; kt += 6) {
        KSTEP_FULL(bb0, bb2, afA, afB, kt);
        KSTEP_FULL(bb1, bb0, afB, afA, kt + 1);
        KSTEP_FULL(bb2, bb1, afA, afB, kt + 2);
        KSTEP_FULL(bb0, bb2, afB, afA, kt + 3);
        KSTEP_FULL(bb1, bb0, afA, afB, kt + 4);
        KSTEP_FULL(bb2, bb1, afB, afA, kt + 5);
    }
    KSTEP_NOB(bb0, afA, afB, 30);      // kt=30: B[30]=bb0, load af[31]
    KSTEP_END(bb1, afB);               // kt=31: B[31]=bb1

    // ---- epilogue: relu+bias, fold layer-3 into rgb partials ---------------
    float rp[8][3];
    #pragma unroll
    for (int i = 0; i < 8; i++) rp[i][0] = rp[i][1] = rp[i][2] = 0.0f;

    #pragma unroll
    for (int m = 0; m < 4; m++)
        #pragma unroll
        for (int nt = 0; nt < 4; nt++) {
            int c0 = wid * 32 + nt * 8 + tg * 2;
            float h0 = relu_f(acc[m][nt][0] + sB2[c0]);
            float h1 = relu_f(acc[m][nt][1] + sB2[c0 + 1]);
            float h2 = relu_f(acc[m][nt][2] + sB2[c0]);
            float h3 = relu_f(acc[m][nt][3] + sB2[c0 + 1]);
            #pragma unroll
            for (int ch = 0; ch < 3; ch++) {
                float w0 = sW3[c0 * 3 + ch], w1 = sW3[(c0 + 1) * 3 + ch];
                rp[m * 2 + 0][ch] = fmaf(h0, w0, fmaf(h1, w1, rp[m * 2 + 0][ch]));
                rp[m * 2 + 1][ch] = fmaf(h2, w0, fmaf(h3, w1, rp[m * 2 + 1][ch]));
            }
        }

    #pragma unroll
    for (int i = 0; i < 8; i++)
        #pragma unroll
        for (int ch = 0; ch < 3; ch++) {
            rp[i][ch] += __shfl_xor_sync(0xffffffffu, rp[i][ch], 1);
            rp[i][ch] += __shfl_xor_sync(0xffffffffu, rp[i][ch], 2);
        }
    if (tg == 0) {
        #pragma unroll
        for (int m = 0; m < 4; m++)
            #pragma unroll
            for (int rh = 0; rh < 2; rh++) {
                int row = m * 16 + rh * 8 + g;
                #pragma unroll
                for (int ch = 0; ch < 3; ch++)
                    sPart[(wid * 64 + row) * 3 + ch] = rp[m * 2 + rh][ch];
            }
    }
    __syncthreads();
    if (tid < 64) {
        #pragma unroll
        for (int ch = 0; ch < 3; ch++) {
            float s = b3f[ch];
            #pragma unroll
            for (int w = 0; w < 16; w++) s += sPart[(w * 64 + tid) * 3 + ch];
            out[ch * N_PIX + pix0 + tid] = s;
        }
    }
}

// ---------------------------------------------------------------------------
extern "C" void kernel_launch(void* const* d_in, const int* in_sizes, int n_in,
                              void* d_out, int out_size) {
    const float* coords = (const float*)d_in[0];
    const float* W1p    = (const float*)d_in[1];
    const float* b1p    = (const float*)d_in[2];
    const float* W2p    = (const float*)d_in[3];
    const float* b2p    = (const float*)d_in[4];
    const float* W1f    = (const float*)d_in[5];
    const float* b1f    = (const float*)d_in[6];
    const float* W2f    = (const float*)d_in[7];
    const float* b2f    = (const float*)d_in[8];
    const float* W3f    = (const float*)d_in[9];
    const float* b3f    = (const float*)d_in[10];
    const int*   idx    = (const int*)d_in[11];
    float*       out    = (float*)d_out;

    cudaFuncSetAttribute(nivr_mma_kernel,
                         cudaFuncAttributeMaxDynamicSharedMemorySize, SMEM_TOT);

    nivr_prep_kernel<<<1537, NTHR>>>(W1p, b1p, W2p, b2p, W1f, b1f, W2f, idx);
    nivr_mma_kernel<<<N_PIX / 64, MTHR, SMEM_TOT>>>(coords, b2f, W3f, b3f, out);
}

// round 12
// speedup vs baseline: 8.4403x; 1.0478x over previous
#include <cuda_runtime.h>
#include <cuda_fp16.h>
#include <math.h>
#include <stdint.h>

#define N_PIX (512 * 512)
#define NTHR  256
#define MTHR  512

// ---------------------------------------------------------------------------
// Device scratch (no allocations allowed)
// ---------------------------------------------------------------------------
__device__ float    g_b1eff[512];        // b1f + phi_t @ W1f[40:,:]
__device__ float    g_Ax[512 * 512];     // posenc_x(c) @ W1f[0:20,:]
__device__ float    g_Ay[512 * 512];     // posenc_y(c) @ W1f[20:40,:]
__device__ uint32_t g_W2H[512 * 256];    // W2 fp16, uint4-fragment-major

// m16n8k16 fp16 mma, fp32 acc
#define MMA_F16(d, a, b0, b1)                                                  \
    asm volatile("mma.sync.aligned.m16n8k16.row.col.f32.f16.f16.f32 "          \
                 "{%0,%1,%2,%3},{%4,%5,%6,%7},{%8,%9},{%0,%1,%2,%3};"          \
                 : "+f"((d)[0]), "+f"((d)[1]), "+f"((d)[2]), "+f"((d)[3])      \
                 : "r"((a).x), "r"((a).y), "r"((a).z), "r"((a).w),             \
                   "r"(b0), "r"(b1))

__device__ __forceinline__ uint32_t h2u(float a, float b) {
    __half2 h = __floats2half2_rn(a, b);
    return *(uint32_t*)&h;
}
__device__ __forceinline__ float relu_f(float x) { return fmaxf(x, 0.0f); }

// ---------------------------------------------------------------------------
// Accurate sin/cos (flag-independent): Cody-Waite in double + Cephes fp32
// ---------------------------------------------------------------------------
__device__ __forceinline__ float trig_eval(float x, int cos_flag) {
    double d  = (double)x * 0.63661977236758134308;
    int    ki = __double2int_rn(d);
    float  rf = (float)((double)x - (double)ki * 1.57079632679489661923);
    int    q  = (ki + cos_flag) & 3;
    float  z  = rf * rf;
    float s = ((-1.9515295891e-4f * z + 8.3321608736e-3f) * z - 1.6666654611e-1f)
                  * z * rf + rf;
    float c = ((2.443315711809948e-5f * z - 1.388731625493765e-3f) * z
                  + 4.166664568298827e-2f) * z * z - 0.5f * z + 1.0f;
    float res = (q & 1) ? c : s;
    return (q & 2) ? -res : res;
}

// ---------------------------------------------------------------------------
// Prep (single launch, 1537 blocks): tables, W2H packing, time branch.
// W2H packing for element (n, k), value W2f[k*512+n]:
//   k16=k>>4, lane=(n&7)*4+((k&7)>>1), reg=(k>>3)&1, np=(n>>4), o=(n>>3)&1
//   uint4 index = (k16*32 + np)*32 + lane,  component = o*2 + reg
// ---------------------------------------------------------------------------
__global__ void nivr_prep_kernel(const float* __restrict__ W1p,
                                 const float* __restrict__ b1p,
                                 const float* __restrict__ W2p,
                                 const float* __restrict__ b2p,
                                 const float* __restrict__ W1f,
                                 const float* __restrict__ b1f,
                                 const float* __restrict__ W2f,
                                 const int*   __restrict__ idx_p) {
    const int b = blockIdx.x, tid = threadIdx.x;
    if (b < 1024) {
        const int axis = b >> 9;
        const int c    = b & 511;
        __shared__ float pe[20];
        if (tid < 20) {
            int l = tid % 10;
            float ang = (((float)c * (1.0f / 512.0f)) * (float)(1 << l))
                            * 3.14159265358979323846f;
            pe[tid] = trig_eval(ang, tid >= 10);
        }
        __syncthreads();
        const float* Wr  = W1f + axis * 20 * 512;
        float*       dst = (axis ? g_Ay : g_Ax) + c * 512;
        for (int j = tid; j < 512; j += NTHR) {
            float acc = 0.0f;
            #pragma unroll
            for (int f = 0; f < 20; f++)
                acc = fmaf(pe[f], Wr[f * 512 + j], acc);
            dst[j] = acc;
        }
    } else if (b < 1536) {
        const int n  = b - 1024;
        const int k  = tid * 2;             // even k; pack (k, k+1)
        float lo = W2f[(size_t)k * 512 + n];
        float hi = W2f[(size_t)(k + 1) * 512 + n];
        int k16  = k >> 4;
        int lane = (n & 7) * 4 + ((k & 7) >> 1);
        int reg  = (k >> 3) & 1;
        int idx4 = (k16 * 32 + (n >> 4)) * 32 + lane;
        int comp = ((n >> 3) & 1) * 2 + reg;
        g_W2H[idx4 * 4 + comp] = h2u(lo, hi);
    } else {
        __shared__ float sr[32];
        __shared__ float sh[256];
        __shared__ float sphi[128];
        float t = (float)(*idx_p) / 300.0f;
        if (tid < 32) {
            int l = tid & 15;
            float ang = (t * (float)(1 << l)) * 3.14159265358979323846f;
            sr[tid] = trig_eval(ang, tid >= 16);
        }
        __syncthreads();
        {
            float acc = b1p[tid];
            #pragma unroll
            for (int k = 0; k < 32; k++)
                acc = fmaf(sr[k], W1p[k * 256 + tid], acc);
            sh[tid] = fmaxf(acc, 0.0f);
        }
        __syncthreads();
        if (tid < 128) {
            float acc = b2p[tid];
            #pragma unroll 4
            for (int k = 0; k < 256; k++)
                acc = fmaf(sh[k], W2p[k * 128 + tid], acc);
            sphi[tid] = acc;
        }
        __syncthreads();
        for (int j = tid; j < 512; j += NTHR) {
            float acc = b1f[j];
            #pragma unroll 4
            for (int k = 0; k < 128; k++)
                acc = fmaf(sphi[k], W1f[(40 + k) * 512 + j], acc);
            g_b1eff[j] = acc;
        }
    }
}

// ---------------------------------------------------------------------------
// Main: CTA = 128 pixels as TWO 64-pixel tiles, 512 threads / 16 warps,
// each warp n32. A double-buffered in smem (2 x 64KB); tile 1's A production
// is interleaved into tile 0's MMA mainloop (produce/compute overlap).
// B triple-buffered (dist 2), A fragments double-buffered (dist 1) in regs.
// ---------------------------------------------------------------------------
#define SA_U4    4096                      /* per tile: 32kt x 4mt x 32lane uint4 */
#define OFF_SA   0
#define OFF_B1   (2 * SA_U4 * 16)          /* 131072 */
#define OFF_B2   (OFF_B1 + 2048)
#define OFF_W3   (OFF_B2 + 2048)
#define OFF_PART (OFF_W3 + 6144)
#define OFF_XY   (OFF_PART + 16 * 64 * 3 * 4)
#define SMEM_TOT (OFF_XY + 1024)

// Produce one A chunk (uint4) for pixel-tile with coord arrays sXt/sYt into
// sAdst. i in [0,8): chunk index for this thread.
__device__ __forceinline__ void produce_chunk(
    uint4* __restrict__ sAdst, const float* __restrict__ sB1,
    const int* __restrict__ sXt, const int* __restrict__ sYt,
    int tid, int i)
{
    const int pkc = tid >> 8;
    const int pkt = (tid >> 7) & 1;
    const int pmt = (tid >> 5) & 3;
    const int pln = tid & 31;
    const int pg  = pln >> 2, ptg = pln & 3;
    const int p0  = pmt * 16 + pg, p1 = p0 + 8;
    const float* ax0 = g_Ax + (size_t)sXt[p0] * 512;
    const float* ay0 = g_Ay + (size_t)sYt[p0] * 512;
    const float* ax1 = g_Ax + (size_t)sXt[p1] * 512;
    const float* ay1 = g_Ay + (size_t)sYt[p1] * 512;
    const int koff = pkt * 16 + ptg * 2;
    const int slot = (pkt * 4 + pmt) * 32 + pln;
    const int kc = i * 2 + pkc;
    const int kb = kc * 32 + koff;
    float2 xa = *(const float2*)(ax0 + kb),     ya = *(const float2*)(ay0 + kb);
    float2 xb = *(const float2*)(ax0 + kb + 8), yb = *(const float2*)(ay0 + kb + 8);
    float2 xc = *(const float2*)(ax1 + kb),     yc = *(const float2*)(ay1 + kb);
    float2 xd = *(const float2*)(ax1 + kb + 8), yd = *(const float2*)(ay1 + kb + 8);
    float2 ba = *(const float2*)(sB1 + kb),     bb = *(const float2*)(sB1 + kb + 8);
    uint4 v;
    v.x = h2u(relu_f(xa.x + ya.x + ba.x), relu_f(xa.y + ya.y + ba.y));
    v.y = h2u(relu_f(xc.x + yc.x + ba.x), relu_f(xc.y + yc.y + ba.y));
    v.z = h2u(relu_f(xb.x + yb.x + bb.x), relu_f(xb.y + yb.y + bb.y));
    v.w = h2u(relu_f(xd.x + yd.x + bb.x), relu_f(xd.y + yd.y + bb.y));
    sAdst[kc * 256 + slot] = v;
}

__global__ __launch_bounds__(MTHR, 1)
void nivr_mma_kernel(const float* __restrict__ coords,
                     const float* __restrict__ b2f,
                     const float* __restrict__ W3f,
                     const float* __restrict__ b3f,
                     float* __restrict__ out) {
    extern __shared__ char smem[];
    uint4* sA4   = (uint4*)(smem + OFF_SA);     // [2][4096]
    float* sB1   = (float*)(smem + OFF_B1);
    float* sB2   = (float*)(smem + OFF_B2);
    float* sW3   = (float*)(smem + OFF_W3);
    float* sPart = (float*)(smem + OFF_PART);   // [16][64][3]
    int*   sX    = (int*)(smem + OFF_XY);       // [128]
    int*   sY    = sX + 128;                    // [128]

    const int tid  = threadIdx.x;
    const int wid  = tid >> 5;            // warpN: 0..15 (cols wid*32..+31)
    const int lane = tid & 31;
    const int g    = lane >> 2;
    const int tg   = lane & 3;
    const int base = blockIdx.x * 128;

    if (tid < 128) {
        sX[tid] = (int)coords[(base + tid) * 2 + 0];
        sY[tid] = (int)coords[(base + tid) * 2 + 1];
    }
    for (int i = tid; i < 512;  i += MTHR) { sB1[i] = g_b1eff[i]; sB2[i] = b2f[i]; }
    for (int i = tid; i < 1536; i += MTHR) sW3[i] = W3f[i];
    __syncthreads();

    // ---- produce tile-0 A up front -----------------------------------------
    #pragma unroll 4
    for (int i = 0; i < 8; i++)
        produce_chunk(sA4, sB1, sX, sY, tid, i);

    const uint4* bbase = (const uint4*)g_W2H + wid * 2 * 32 + lane;

    #pragma unroll 1
    for (int t = 0; t < 2; t++) {
        __syncthreads();                   // A[t] ready; sPart safe to reuse
        const uint4* sAcur = sA4 + t * SA_U4;

        float acc[4][4][4];
        #pragma unroll
        for (int m = 0; m < 4; m++)
            #pragma unroll
            for (int n = 0; n < 4; n++)
                acc[m][n][0] = acc[m][n][1] = acc[m][n][2] = acc[m][n][3] = 0.0f;

        uint4 bb0[2], bb1[2], bb2[2];      // B[j] lives in bb[j % 3]
        uint4 afA[4], afB[4];              // af[kt]: afA even kt, afB odd kt
        #pragma unroll
        for (int np = 0; np < 2; np++) {
            bb0[np] = bbase[np * 32];
            bb1[np] = bbase[1024 + np * 32];
        }
        #pragma unroll
        for (int m = 0; m < 4; m++)
            afA[m] = sAcur[m * 32 + lane];

#define KSTEP_FULL(USEB, LDB, USEA, LDA, KT)                                   \
    {                                                                          \
        _Pragma("unroll")                                                      \
        for (int np = 0; np < 2; np++)                                         \
            LDB[np] = bbase[((KT) + 2) * 1024 + np * 32];                      \
        _Pragma("unroll")                                                      \
        for (int m = 0; m < 4; m++)                                            \
            LDA[m] = sAcur[((KT) + 1) * 128 + m * 32 + lane];                  \
        _Pragma("unroll")                                                      \
        for (int np = 0; np < 2; np++)                                         \
            _Pragma("unroll")                                                  \
            for (int m = 0; m < 4; m++) {                                      \
                MMA_F16(acc[m][np * 2 + 0], USEA[m], USEB[np].x, USEB[np].y);  \
                MMA_F16(acc[m][np * 2 + 1], USEA[m], USEB[np].z, USEB[np].w);  \
            }                                                                  \
    }
#define KSTEP_NOB(USEB, USEA, LDA, KT)                                         \
    {                                                                          \
        _Pragma("unroll")                                                      \
        for (int m = 0; m < 4; m++)                                            \
            LDA[m] = sAcur[((KT) + 1) * 128 + m * 32 + lane];                  \
        _Pragma("unroll")                                                      \
        for (int np = 0; np < 2; np++)                                         \
            _Pragma("unroll")                                                  \
            for (int m = 0; m < 4; m++) {                                      \
                MMA_F16(acc[m][np * 2 + 0], USEA[m], USEB[np].x, USEB[np].y);  \
                MMA_F16(acc[m][np * 2 + 1], USEA[m], USEB[np].z, USEB[np].w);  \
            }                                                                  \
    }
#define KSTEP_END(USEB, USEA)                                                  \
    {                                                                          \
        _Pragma("unroll")                                                      \
        for (int np = 0; np < 2; np++)                                         \
            _Pragma("unroll")                                                  \
            for (int m = 0; m < 4; m++) {                                      \
                MMA_F16(acc[m][np * 2 + 0], USEA[m], USEB[np].x, USEB[np].y);  \
                MMA_F16(acc[m][np * 2 + 1], USEA[m], USEB[np].z, USEB[np].w);  \
            }                                                                  \
    }

        // 6-step rotation; during tile 0, weave in tile-1 A production
        // (8 produce iterations at kt = 0,3,6,9,12,15,18,21).
        int pi = 0;
        #pragma unroll 1
        for (int kt = 0; kt < 30; kt += 6) {
            KSTEP_FULL(bb0, bb2, afA, afB, kt);
            if (t == 0 && pi < 8) { produce_chunk(sA4 + SA_U4, sB1, sX + 64, sY + 64, tid, pi); pi++; }
            KSTEP_FULL(bb1, bb0, afB, afA, kt + 1);
            KSTEP_FULL(bb2, bb1, afA, afB, kt + 2);
            KSTEP_FULL(bb0, bb2, afB, afA, kt + 3);
            if (t == 0 && pi < 8) { produce_chunk(sA4 + SA_U4, sB1, sX + 64, sY + 64, tid, pi); pi++; }
            KSTEP_FULL(bb1, bb0, afA, afB, kt + 4);
            KSTEP_FULL(bb2, bb1, afB, afA, kt + 5);
        }
        KSTEP_NOB(bb0, afA, afB, 30);
        KSTEP_END(bb1, afB);

        // ---- epilogue: relu+bias, fold layer-3 into rgb partials -----------
        float rp[8][3];
        #pragma unroll
        for (int i = 0; i < 8; i++) rp[i][0] = rp[i][1] = rp[i][2] = 0.0f;

        #pragma unroll
        for (int m = 0; m < 4; m++)
            #pragma unroll
            for (int nt = 0; nt < 4; nt++) {
                int c0 = wid * 32 + nt * 8 + tg * 2;
                float h0 = relu_f(acc[m][nt][0] + sB2[c0]);
                float h1 = relu_f(acc[m][nt][1] + sB2[c0 + 1]);
                float h2 = relu_f(acc[m][nt][2] + sB2[c0]);
                float h3 = relu_f(acc[m][nt][3] + sB2[c0 + 1]);
                #pragma unroll
                for (int ch = 0; ch < 3; ch++) {
                    float w0 = sW3[c0 * 3 + ch], w1 = sW3[(c0 + 1) * 3 + ch];
                    rp[m * 2 + 0][ch] = fmaf(h0, w0, fmaf(h1, w1, rp[m * 2 + 0][ch]));
                    rp[m * 2 + 1][ch] = fmaf(h2, w0, fmaf(h3, w1, rp[m * 2 + 1][ch]));
                }
            }

        #pragma unroll
        for (int i = 0; i < 8; i++)
            #pragma unroll
            for (int ch = 0; ch < 3; ch++) {
                rp[i][ch] += __shfl_xor_sync(0xffffffffu, rp[i][ch], 1);
                rp[i][ch] += __shfl_xor_sync(0xffffffffu, rp[i][ch], 2);
            }
        if (tg == 0) {
            #pragma unroll
            for (int m = 0; m < 4; m++)
                #pragma unroll
                for (int rh = 0; rh < 2; rh++) {
                    int row = m * 16 + rh * 8 + g;
                    #pragma unroll
                    for (int ch = 0; ch < 3; ch++)
                        sPart[(wid * 64 + row) * 3 + ch] = rp[m * 2 + rh][ch];
                }
        }
        __syncthreads();
        if (tid < 64) {
            #pragma unroll
            for (int ch = 0; ch < 3; ch++) {
                float s = b3f[ch];
                #pragma unroll
                for (int w = 0; w < 16; w++) s += sPart[(w * 64 + tid) * 3 + ch];
                out[ch * N_PIX + base + t * 64 + tid] = s;
            }
        }
    }
}

// ---------------------------------------------------------------------------
extern "C" void kernel_launch(void* const* d_in, const int* in_sizes, int n_in,
                              void* d_out, int out_size) {
    const float* coords = (const float*)d_in[0];
    const float* W1p    = (const float*)d_in[1];
    const float* b1p    = (const float*)d_in[2];
    const float* W2p    = (const float*)d_in[3];
    const float* b2p    = (const float*)d_in[4];
    const float* W1f    = (const float*)d_in[5];
    const float* b1f    = (const float*)d_in[6];
    const float* W2f    = (const float*)d_in[7];
    const float* b2f    = (const float*)d_in[8];
    const float* W3f    = (const float*)d_in[9];
    const float* b3f    = (const float*)d_in[10];
    const int*   idx    = (const int*)d_in[11];
    float*       out    = (float*)d_out;

    cudaFuncSetAttribute(nivr_mma_kernel,
                         cudaFuncAttributeMaxDynamicSharedMemorySize, SMEM_TOT);

    nivr_prep_kernel<<<1537, NTHR>>>(W1p, b1p, W2p, b2p, W1f, b1f, W2f, idx);
    nivr_mma_kernel<<<N_PIX / 128, MTHR, SMEM_TOT>>>(coords, b2f, W3f, b3f, out);
}